// round 11
// baseline (speedup 1.0000x reference)
#include <cuda_runtime.h>
#include <cuda_fp16.h>
#include <cstdint>

// ---------------------------------------------------------------------------
// AttentionBlock, fully tensor-core (fp16 mma.m16n8k16, fp32 accum):
//   GroupNorm (fp16 transposed) -> QKV mma GEMM (3-stage cp.async ring)
//   -> FA-2 flash attention (register P, ex2.f16x2, HADD2 row sums,
//      3-stage cp.async ring, 1 barrier/tile) -> proj mma GEMM + residual.
// B=4, C=256, L=4096, 4 heads, d=64.
// ---------------------------------------------------------------------------

namespace {
constexpr int B_  = 4;
constexpr int C_  = 256;
constexpr int L_  = 4096;
constexpr int G_  = 32;
constexpr int NH_ = 4;
constexpr int CPG_ = C_ / G_;
constexpr float QSCALE = 0.125f * 1.4426950408889634f;   // d^-0.5 * log2(e)
// attention smem: 3 stages x (K 64x72 + V 64x72) halves; stage = 4608 u32
constexpr int ATTN_SMEM = 3 * 4608 * 4;                  // 55296 B
// gemm smem: 3 stages x (A 128x72 + B 128x72) halves; stage = 9216 u32
constexpr int GEMM_SMEM = 3 * 9216 * 4;                  // 110592 B
}

// ---- fp16 mma (fp32 accumulate) ----
__device__ __forceinline__ void mma_f16(float c[4], const uint32_t a[4],
                                        uint32_t b0, uint32_t b1) {
    asm volatile(
        "mma.sync.aligned.m16n8k16.row.col.f32.f16.f16.f32 "
        "{%0,%1,%2,%3},{%4,%5,%6,%7},{%8,%9},{%0,%1,%2,%3};"
        : "+f"(c[0]), "+f"(c[1]), "+f"(c[2]), "+f"(c[3])
        : "r"(a[0]), "r"(a[1]), "r"(a[2]), "r"(a[3]), "r"(b0), "r"(b1));
}
__device__ __forceinline__ uint32_t h2u(float x, float y) {
    __half2 h = __floats2half2_rn(x, y);
    return *reinterpret_cast<uint32_t*>(&h);
}
__device__ __forceinline__ uint32_t ex2h2(float x, float y) {
    uint32_t h = h2u(x, y), r;
    asm("ex2.approx.f16x2 %0, %1;" : "=r"(r) : "r"(h));
    return r;
}
__device__ __forceinline__ float2 h2sumf(uint32_t a, uint32_t b) {
    __half2 s = __hadd2(*reinterpret_cast<__half2*>(&a),
                        *reinterpret_cast<__half2*>(&b));
    return __half22float2(s);
}
__device__ __forceinline__ uint32_t smem_u32p(const void* p) {
    uint32_t a;
    asm("{ .reg .u64 t; cvta.to.shared.u64 t, %1; cvt.u32.u64 %0, t; }" : "=r"(a) : "l"(p));
    return a;
}
#define CP_ASYNC16(dst, src) \
    asm volatile("cp.async.cg.shared.global [%0], [%1], 16;" :: "r"(dst), "l"(src))
#define CP_COMMIT() asm volatile("cp.async.commit_group;")

// ---- scratch (device globals) ----
__device__ __half g_ht[B_ * L_ * C_];        // GN output transposed (b, l, c)
__device__ __half g_q [B_ * NH_ * L_ * 64];  // (bh, l, d), prescaled by QSCALE
__device__ __half g_k [B_ * NH_ * L_ * 64];  // (bh, l, d)
__device__ __half g_v [B_ * NH_ * 64 * L_];  // (bh, d, l)
__device__ __half g_ot[B_ * L_ * C_];        // attention out transposed (b, l, c)
__device__ __half g_wh[768 * 256];           // qkv weights fp16 (Q rows prescaled)
__device__ __half g_wp[256 * 256];           // proj weights fp16
__device__ float  g_bs[768];                 // qkv bias (Q prescaled)
__device__ float  g_mean[B_ * G_];
__device__ float  g_rstd[B_ * G_];

// ---------------------------------------------------------------------------
// GroupNorm stats
// ---------------------------------------------------------------------------
__global__ void gn_stats_kernel(const float* __restrict__ x) {
    const int bg = blockIdx.x;
    const float4* p = reinterpret_cast<const float4*>(x) + (size_t)bg * (CPG_ * L_ / 4);
    float s = 0.f, ss = 0.f;
    for (int i = threadIdx.x; i < CPG_ * L_ / 4; i += blockDim.x) {
        float4 v = p[i];
        s  += v.x + v.y + v.z + v.w;
        ss += v.x * v.x + v.y * v.y + v.z * v.z + v.w * v.w;
    }
#pragma unroll
    for (int o = 16; o > 0; o >>= 1) {
        s  += __shfl_xor_sync(0xffffffffu, s, o);
        ss += __shfl_xor_sync(0xffffffffu, ss, o);
    }
    __shared__ float sh_s[8], sh_ss[8];
    const int w = threadIdx.x >> 5;
    if ((threadIdx.x & 31) == 0) { sh_s[w] = s; sh_ss[w] = ss; }
    __syncthreads();
    if (threadIdx.x == 0) {
        float S = 0.f, SS = 0.f;
#pragma unroll
        for (int i = 0; i < 8; i++) { S += sh_s[i]; SS += sh_ss[i]; }
        const float inv = 1.f / (float)(CPG_ * L_);
        const float mean = S * inv;
        const float var  = SS * inv - mean * mean;
        g_mean[bg] = mean;
        g_rstd[bg] = rsqrtf(var + 1e-5f);
    }
}

// ---------------------------------------------------------------------------
// GroupNorm apply, emitting fp16 h^T as (b, l, c)
// ---------------------------------------------------------------------------
__global__ void gn_apply_t_kernel(const float* __restrict__ x,
                                  const float* __restrict__ w,
                                  const float* __restrict__ bvec) {
    __shared__ __half Ts[64 * 40];
    const int b  = blockIdx.z;
    const int c0 = blockIdx.y * 32;
    const int l0 = blockIdx.x * 64;
    const int tid = threadIdx.x;
#pragma unroll
    for (int i = 0; i < 2; i++) {
        const int e = tid + i * 256;
        const int r = e >> 4;
        const int l4 = (e & 15) * 4;
        const int c = c0 + r;
        const int bg = b * G_ + (c >> 3);
        const float sc = g_rstd[bg] * w[c];
        const float sh = bvec[c] - g_mean[bg] * sc;
        float4 v = *reinterpret_cast<const float4*>(
            x + ((size_t)b * C_ + c) * L_ + l0 + l4);
        Ts[(l4 + 0) * 40 + r] = __float2half_rn(v.x * sc + sh);
        Ts[(l4 + 1) * 40 + r] = __float2half_rn(v.y * sc + sh);
        Ts[(l4 + 2) * 40 + r] = __float2half_rn(v.z * sc + sh);
        Ts[(l4 + 3) * 40 + r] = __float2half_rn(v.w * sc + sh);
    }
    __syncthreads();
    const int r = tid >> 2;
    const int q4 = (tid & 3) * 8;
    *reinterpret_cast<uint4*>(g_ht + ((size_t)b * L_ + l0 + r) * C_ + c0 + q4) =
        *reinterpret_cast<const uint4*>(Ts + r * 40 + q4);
}

// ---------------------------------------------------------------------------
// weight/bias conversion
// ---------------------------------------------------------------------------
__global__ void wconv_kernel(const float* __restrict__ qkvw,
                             const float* __restrict__ projw,
                             const float* __restrict__ qkvb) {
    const int row = blockIdx.x, t = threadIdx.x;
    if (row < 768) {
        const float s = (row < 256) ? QSCALE : 1.f;
        g_wh[row * 256 + t] = __float2half_rn(qkvw[row * 256 + t] * s);
        if (t == 0) g_bs[row] = qkvb[row] * s;
    } else {
        const int r = row - 768;
        g_wp[r * 256 + t] = __float2half_rn(projw[r * 256 + t]);
    }
}

// ---------------------------------------------------------------------------
// QKV GEMM (fp16 mma, 3-stage cp.async ring over 4 k-chunks).
// grid (L/128, 6, B), 256 threads. Epilogue routes Q,K -> (bh,l,d),
// V -> (bh,d,l).
// ---------------------------------------------------------------------------
__global__ void __launch_bounds__(256) qkv_mma_kernel() {
    extern __shared__ __align__(16) char smraw[];
    uint32_t* smu = reinterpret_cast<uint32_t*>(smraw);
    const uint32_t sb = smem_u32p(smraw);
    __half* Csh = reinterpret_cast<__half*>(smraw);
    uint32_t* Csu = reinterpret_cast<uint32_t*>(smraw);

    const int tid = threadIdx.x, wid = tid >> 5, lane = tid & 31;
    const int lg = lane >> 2, lt = lane & 3;
    const int nt = blockIdx.x, mt = blockIdx.y, b = blockIdx.z;
    const int m0 = mt * 128, n0g = nt * 128;
    const int moff = (wid & 3) * 32, noff = (wid >> 2) * 64;
    const __half* wsrc = g_wh;
    const __half* hsrc = g_ht + ((size_t)b * L_ + n0g) * 256;

    auto issueAB = [&](int kc, uint32_t ub /*u32 stage base*/) {
#pragma unroll
        for (int i = 0; i < 4; i++) {
            const int e = tid + i * 256;
            const int r = e >> 3, c8 = (e & 7) * 8;
            CP_ASYNC16(sb + ub * 4 + r * 144 + c8 * 2,
                       wsrc + (size_t)(m0 + r) * 256 + kc * 64 + c8);
            CP_ASYNC16(sb + (ub + 4608) * 4 + r * 144 + c8 * 2,
                       hsrc + (size_t)r * 256 + kc * 64 + c8);
        }
        CP_COMMIT();
    };

    issueAB(0, 0);
    issueAB(1, 9216);

    float oc[2][8][4] = {};
    uint32_t scb = 0, snb = 18432;
    for (int k = 0; k < 4; k++) {
        if (k < 3) asm volatile("cp.async.wait_group 1;" ::: "memory");
        else       asm volatile("cp.async.wait_group 0;" ::: "memory");
        __syncthreads();
        if (k + 2 < 4) issueAB(k + 2, snb);
        const uint32_t* Asu = smu + scb;
        const uint32_t* Bsu = smu + scb + 4608;
#pragma unroll
        for (int kc = 0; kc < 4; kc++) {
            uint32_t a[2][4];
#pragma unroll
            for (int m = 0; m < 2; m++) {
                const int r0 = moff + m * 16 + lg;
                a[m][0] = Asu[r0 * 36 + kc * 8 + lt];
                a[m][1] = Asu[(r0 + 8) * 36 + kc * 8 + lt];
                a[m][2] = Asu[r0 * 36 + kc * 8 + lt + 4];
                a[m][3] = Asu[(r0 + 8) * 36 + kc * 8 + lt + 4];
            }
#pragma unroll
            for (int n = 0; n < 8; n++) {
                const int brow = noff + n * 8 + lg;
                const uint32_t b0 = Bsu[brow * 36 + kc * 8 + lt];
                const uint32_t b1 = Bsu[brow * 36 + kc * 8 + lt + 4];
                mma_f16(oc[0][n], a[0], b0, b1);
                mma_f16(oc[1][n], a[1], b0, b1);
            }
        }
        scb = (scb == 18432) ? 0 : scb + 9216;
        snb = (snb == 18432) ? 0 : snb + 9216;
    }
    __syncthreads();

    const int sel = mt >> 1;
    const int h0 = (mt & 1) * 2;
    float bv[2][2];
#pragma unroll
    for (int m = 0; m < 2; m++) {
        bv[m][0] = g_bs[m0 + moff + m * 16 + lg];
        bv[m][1] = g_bs[m0 + moff + m * 16 + lg + 8];
    }

    if (sel < 2) {
        // transposed stage: Csh[l][m], stride 136
#pragma unroll
        for (int m = 0; m < 2; m++) {
            const int r = moff + m * 16 + lg;
#pragma unroll
            for (int n = 0; n < 8; n++) {
                const int col = noff + n * 8 + 2 * lt;
                Csh[col * 136 + r]           = __float2half_rn(oc[m][n][0] + bv[m][0]);
                Csh[(col + 1) * 136 + r]     = __float2half_rn(oc[m][n][1] + bv[m][0]);
                Csh[col * 136 + r + 8]       = __float2half_rn(oc[m][n][2] + bv[m][1]);
                Csh[(col + 1) * 136 + r + 8] = __float2half_rn(oc[m][n][3] + bv[m][1]);
            }
        }
        __syncthreads();
        __half* dst = (sel == 0 ? g_q : g_k);
#pragma unroll
        for (int i = 0; i < 8; i++) {
            const int e = tid + i * 256;
            const int l = e >> 4;
            const int seg = e & 15;
            const int hd = seg >> 3, q8 = (seg & 7) * 8;
            *reinterpret_cast<uint4*>(
                dst + ((size_t)(b * NH_ + h0 + hd) * L_ + n0g + l) * 64 + q8) =
                *reinterpret_cast<const uint4*>(Csh + l * 136 + hd * 64 + q8);
        }
    } else {
        // natural stage: Csh[m][n], stride 136 (68 u32)
#pragma unroll
        for (int m = 0; m < 2; m++) {
            const int r = moff + m * 16 + lg;
#pragma unroll
            for (int n = 0; n < 8; n++) {
                const int cu = (noff >> 1) + n * 4 + lt;
                Csu[r * 68 + cu]       = h2u(oc[m][n][0] + bv[m][0], oc[m][n][1] + bv[m][0]);
                Csu[(r + 8) * 68 + cu] = h2u(oc[m][n][2] + bv[m][1], oc[m][n][3] + bv[m][1]);
            }
        }
        __syncthreads();
#pragma unroll
        for (int i = 0; i < 8; i++) {
            const int e = tid + i * 256;
            const int r = e >> 4;
            const int c8 = (e & 15) * 8;
            const int hd = r >> 6, d = r & 63;
            *reinterpret_cast<uint4*>(
                g_v + ((size_t)((b * NH_ + h0 + hd) * 64 + d)) * L_ + n0g + c8) =
                *reinterpret_cast<const uint4*>(Csh + r * 136 + c8);
        }
    }
}

// ---------------------------------------------------------------------------
// Flash attention (FA-2 register P). CTA = 128 thr, 128 queries, one bh.
// 64-key tiles, 3-stage cp.async ring, ONE barrier per tile. Row sums via
// HADD2 on the P fragments (no ones-row). log2-domain logits -> ex2.f16x2.
// ---------------------------------------------------------------------------
__global__ void __launch_bounds__(128, 3) attn_kernel(__half* __restrict__ ot) {
    extern __shared__ __align__(16) __half smh[];
    uint32_t* smu = reinterpret_cast<uint32_t*>(smh);
    const uint32_t sb = smem_u32p(smh);

    const int tid = threadIdx.x, wid = tid >> 5, lane = tid & 31;
    const int lg = lane >> 2, lt = lane & 3;
    const int qb = wid * 32;
    const int l0 = blockIdx.x * 128;
    const int bh = blockIdx.y, b = bh >> 2, head = bh & 3;
    const __half* qg = g_q + ((size_t)bh * L_ + l0) * 64;
    const __half* kg = g_k + (size_t)bh * L_ * 64;
    const __half* vg = g_v + (size_t)bh * 64 * L_;

    // ---- stage Q (128 x 64) into stage-2 region, extract A-fragments ----
#pragma unroll
    for (int i = 0; i < 8; i++) {
        const int e = tid + i * 128;
        const int r = e >> 3, c8 = (e & 7) * 8;
        *reinterpret_cast<uint4*>(smh + 18432 + r * 72 + c8) =
            *reinterpret_cast<const uint4*>(qg + (size_t)r * 64 + c8);
    }
    __syncthreads();
    uint32_t qa[2][4][4];
    {
        const uint32_t* Qu = smu + 9216;
#pragma unroll
        for (int m = 0; m < 2; m++) {
            const int r0 = qb + m * 16 + lg;
#pragma unroll
            for (int kc = 0; kc < 4; kc++) {
                qa[m][kc][0] = Qu[r0 * 36 + kc * 8 + lt];
                qa[m][kc][1] = Qu[(r0 + 8) * 36 + kc * 8 + lt];
                qa[m][kc][2] = Qu[r0 * 36 + kc * 8 + lt + 4];
                qa[m][kc][3] = Qu[(r0 + 8) * 36 + kc * 8 + lt + 4];
            }
        }
    }

    auto issue = [&](int tile, uint32_t ub /*u32 stage base*/) {
        const __half* ks = kg + (size_t)tile * 64 * 64;
        const __half* vs = vg + tile * 64;
#pragma unroll
        for (int i = 0; i < 4; i++) {
            const int e = tid + i * 128;
            const int r = e >> 3, c8 = (e & 7) * 8;
            CP_ASYNC16(sb + ub * 4 + r * 144 + c8 * 2,
                       ks + (size_t)r * 64 + c8);
            CP_ASYNC16(sb + (ub + 2304) * 4 + r * 144 + c8 * 2,
                       vs + (size_t)r * L_ + c8);
        }
        CP_COMMIT();
    };
    issue(0, 0);
    issue(1, 4608);

    float oc[2][8][4] = {};
    float rs[2][2] = {{0.f, 0.f}, {0.f, 0.f}};
    uint32_t scb = 0, snb = 9216;

    for (int it = 0; it < 64; ++it) {
        if (it < 63) asm volatile("cp.async.wait_group 1;" ::: "memory");
        else         asm volatile("cp.async.wait_group 0;" ::: "memory");
        __syncthreads();
        if (it + 2 < 64) issue(it + 2, snb);
        const uint32_t* Ku = smu + scb;
        const uint32_t* Vu = Ku + 2304;

#pragma unroll
        for (int kb = 0; kb < 4; kb++) {
            float ca0[4] = {}, cb0[4] = {}, ca1[4] = {}, cb1[4] = {};
            const int kr0 = kb * 16 + lg, kr1 = kr0 + 8;
#pragma unroll
            for (int kc = 0; kc < 4; kc++) {
                const uint32_t b0 = Ku[kr0 * 36 + kc * 8 + lt];
                const uint32_t b1 = Ku[kr0 * 36 + kc * 8 + lt + 4];
                mma_f16(ca0, qa[0][kc], b0, b1);
                mma_f16(cb0, qa[1][kc], b0, b1);
                const uint32_t d0 = Ku[kr1 * 36 + kc * 8 + lt];
                const uint32_t d1 = Ku[kr1 * 36 + kc * 8 + lt + 4];
                mma_f16(ca1, qa[0][kc], d0, d1);
                mma_f16(cb1, qa[1][kc], d0, d1);
            }
            uint32_t pa0[4] = {ex2h2(ca0[0], ca0[1]), ex2h2(ca0[2], ca0[3]),
                               ex2h2(ca1[0], ca1[1]), ex2h2(ca1[2], ca1[3])};
            uint32_t pa1[4] = {ex2h2(cb0[0], cb0[1]), ex2h2(cb0[2], cb0[3]),
                               ex2h2(cb1[0], cb1[1]), ex2h2(cb1[2], cb1[3])};
            // row sums from the same fp16 P the MMA consumes
            {
                float2 f;
                f = h2sumf(pa0[0], pa0[2]); rs[0][0] += f.x + f.y;
                f = h2sumf(pa0[1], pa0[3]); rs[0][1] += f.x + f.y;
                f = h2sumf(pa1[0], pa1[2]); rs[1][0] += f.x + f.y;
                f = h2sumf(pa1[1], pa1[3]); rs[1][1] += f.x + f.y;
            }
#pragma unroll
            for (int n = 0; n < 8; n++) {
                const int vrow = n * 8 + lg;
                const uint32_t b0 = Vu[vrow * 36 + kb * 8 + lt];
                const uint32_t b1 = Vu[vrow * 36 + kb * 8 + lt + 4];
                mma_f16(oc[0][n], pa0, b0, b1);
                mma_f16(oc[1][n], pa1, b0, b1);
            }
        }
        scb = (scb == 9216) ? 0 : scb + 4608;
        snb = (snb == 9216) ? 0 : snb + 4608;
    }

    // ---- quad-reduce row sums, normalize ----
    float inv[2][2];
#pragma unroll
    for (int m = 0; m < 2; m++)
#pragma unroll
        for (int r = 0; r < 2; r++) {
            float v = rs[m][r];
            v += __shfl_xor_sync(0xffffffffu, v, 1);
            v += __shfl_xor_sync(0xffffffffu, v, 2);
            inv[m][r] = 1.f / v;
        }

    // ---- stage O (l, d) fp16 in stage-0 region, write (b, l, c) rows ----
    __syncthreads();
#pragma unroll
    for (int m = 0; m < 2; m++) {
        const int qrow = qb + m * 16 + lg;
#pragma unroll
        for (int n = 0; n < 8; n++) {
            smu[qrow * 36 + n * 4 + lt] =
                h2u(oc[m][n][0] * inv[m][0], oc[m][n][1] * inv[m][0]);
            smu[(qrow + 8) * 36 + n * 4 + lt] =
                h2u(oc[m][n][2] * inv[m][1], oc[m][n][3] * inv[m][1]);
        }
    }
    __syncthreads();
    __half* otp = ot + ((size_t)b * L_ + l0) * C_ + head * 64;
#pragma unroll
    for (int i = 0; i < 8; i++) {
        const int e = tid + i * 128;
        const int l = e >> 3, c8 = (e & 7) * 8;
        *reinterpret_cast<uint4*>(otp + (size_t)l * C_ + c8) =
            *reinterpret_cast<const uint4*>(smh + l * 72 + c8);
    }
}

// ---------------------------------------------------------------------------
// proj GEMM (fp16 mma, 3-stage cp.async ring) + bias + residual, fp32 out
// ---------------------------------------------------------------------------
__global__ void __launch_bounds__(256) proj_mma_kernel(
    const float* __restrict__ projb, const float* __restrict__ x,
    float* __restrict__ out)
{
    extern __shared__ __align__(16) char smraw[];
    uint32_t* smu = reinterpret_cast<uint32_t*>(smraw);
    const uint32_t sb = smem_u32p(smraw);

    const int tid = threadIdx.x, wid = tid >> 5, lane = tid & 31;
    const int lg = lane >> 2, lt = lane & 3;
    const int nt = blockIdx.x, mt = blockIdx.y, b = blockIdx.z;
    const int m0 = mt * 128, n0g = nt * 128;
    const int moff = (wid & 3) * 32, noff = (wid >> 2) * 64;
    const __half* wsrc = g_wp;
    const __half* osrc = g_ot + ((size_t)b * L_ + n0g) * 256;

    auto issueAB = [&](int kc, uint32_t ub) {
#pragma unroll
        for (int i = 0; i < 4; i++) {
            const int e = tid + i * 256;
            const int r = e >> 3, c8 = (e & 7) * 8;
            CP_ASYNC16(sb + ub * 4 + r * 144 + c8 * 2,
                       wsrc + (size_t)(m0 + r) * 256 + kc * 64 + c8);
            CP_ASYNC16(sb + (ub + 4608) * 4 + r * 144 + c8 * 2,
                       osrc + (size_t)r * 256 + kc * 64 + c8);
        }
        CP_COMMIT();
    };
    issueAB(0, 0);
    issueAB(1, 9216);

    float oc[2][8][4] = {};
    uint32_t scb = 0, snb = 18432;
    for (int k = 0; k < 4; k++) {
        if (k < 3) asm volatile("cp.async.wait_group 1;" ::: "memory");
        else       asm volatile("cp.async.wait_group 0;" ::: "memory");
        __syncthreads();
        if (k + 2 < 4) issueAB(k + 2, snb);
        const uint32_t* Asu = smu + scb;
        const uint32_t* Bsu = smu + scb + 4608;
#pragma unroll
        for (int kc = 0; kc < 4; kc++) {
            uint32_t a[2][4];
#pragma unroll
            for (int m = 0; m < 2; m++) {
                const int r0 = moff + m * 16 + lg;
                a[m][0] = Asu[r0 * 36 + kc * 8 + lt];
                a[m][1] = Asu[(r0 + 8) * 36 + kc * 8 + lt];
                a[m][2] = Asu[r0 * 36 + kc * 8 + lt + 4];
                a[m][3] = Asu[(r0 + 8) * 36 + kc * 8 + lt + 4];
            }
#pragma unroll
            for (int n = 0; n < 8; n++) {
                const int brow = noff + n * 8 + lg;
                const uint32_t b0 = Bsu[brow * 36 + kc * 8 + lt];
                const uint32_t b1 = Bsu[brow * 36 + kc * 8 + lt + 4];
                mma_f16(oc[0][n], a[0], b0, b1);
                mma_f16(oc[1][n], a[1], b0, b1);
            }
        }
        scb = (scb == 18432) ? 0 : scb + 9216;
        snb = (snb == 18432) ? 0 : snb + 9216;
    }
    // direct epilogue: bias + residual + fp32 store
#pragma unroll
    for (int m = 0; m < 2; m++) {
        const int crow = m0 + moff + m * 16 + lg;
        const float b0v = projb[crow], b1v = projb[crow + 8];
        const float* xp0 = x   + ((size_t)b * C_ + crow) * L_;
        float*       op0 = out + ((size_t)b * C_ + crow) * L_;
#pragma unroll
        for (int n = 0; n < 8; n++) {
            const int col = n0g + noff + n * 8 + 2 * lt;
            float2 xr = *reinterpret_cast<const float2*>(xp0 + col);
            *reinterpret_cast<float2*>(op0 + col) =
                make_float2(oc[m][n][0] + b0v + xr.x, oc[m][n][1] + b0v + xr.y);
            float2 xr2 = *reinterpret_cast<const float2*>(xp0 + 8 * L_ + col);
            *reinterpret_cast<float2*>(op0 + 8 * L_ + col) =
                make_float2(oc[m][n][2] + b1v + xr2.x, oc[m][n][3] + b1v + xr2.y);
        }
    }
}

// ---------------------------------------------------------------------------
// Host launcher
// ---------------------------------------------------------------------------
extern "C" void kernel_launch(void* const* d_in, const int* in_sizes, int n_in,
                              void* d_out, int out_size) {
    (void)in_sizes; (void)n_in; (void)out_size;
    const float* x      = (const float*)d_in[0];
    const float* gn_w   = (const float*)d_in[1];
    const float* gn_b   = (const float*)d_in[2];
    const float* qkv_w  = (const float*)d_in[3];
    const float* qkv_b  = (const float*)d_in[4];
    const float* proj_w = (const float*)d_in[5];
    const float* proj_b = (const float*)d_in[6];
    float* out = (float*)d_out;

    void* pot;
    cudaGetSymbolAddress(&pot, g_ot);
    __half* ot = (__half*)pot;

    // 1) GroupNorm -> fp16 transposed h
    gn_stats_kernel<<<B_ * G_, 256>>>(x);
    gn_apply_t_kernel<<<dim3(L_ / 64, C_ / 32, B_), 256>>>(x, gn_w, gn_b);

    // weight conversion
    wconv_kernel<<<1024, 256>>>(qkv_w, proj_w, qkv_b);

    // 2) QKV mma GEMM -> fp16 Q/K/V in attention layouts
    cudaFuncSetAttribute(qkv_mma_kernel,
                         cudaFuncAttributeMaxDynamicSharedMemorySize, GEMM_SMEM);
    qkv_mma_kernel<<<dim3(L_ / 128, 6, B_), 256, GEMM_SMEM>>>();

    // 3) Attention
    cudaFuncSetAttribute(attn_kernel,
                         cudaFuncAttributeMaxDynamicSharedMemorySize, ATTN_SMEM);
    attn_kernel<<<dim3(L_ / 128, B_ * NH_), 128, ATTN_SMEM>>>(ot);

    // 4) proj mma GEMM + bias + residual
    cudaFuncSetAttribute(proj_mma_kernel,
                         cudaFuncAttributeMaxDynamicSharedMemorySize, GEMM_SMEM);
    proj_mma_kernel<<<dim3(L_ / 128, 2, B_), 256, GEMM_SMEM>>>(proj_b, x, out);
}

// round 12
// speedup vs baseline: 1.0149x; 1.0149x over previous
#include <cuda_runtime.h>
#include <cuda_fp16.h>
#include <cstdint>

// ---------------------------------------------------------------------------
// AttentionBlock, fully tensor-core (fp16 mma.m16n8k16, fp32 accum):
//   GroupNorm (fp16 transposed) -> QKV mma GEMM (3-stage cp.async ring)
//   -> FA-2 flash attention (register P, ex2.f16x2, HADD2 row sums,
//      R9 double-buffer protocol) -> proj mma GEMM + residual.
// B=4, C=256, L=4096, 4 heads, d=64.
// ---------------------------------------------------------------------------

namespace {
constexpr int B_  = 4;
constexpr int C_  = 256;
constexpr int L_  = 4096;
constexpr int G_  = 32;
constexpr int NH_ = 4;
constexpr int CPG_ = C_ / G_;
constexpr float QSCALE = 0.125f * 1.4426950408889634f;   // d^-0.5 * log2(e)
// attention smem (halves): K0, K1, V0, V1 tiles of 64x72
constexpr int KOFF0 = 0;
constexpr int KOFF1 = 4608;
constexpr int VOFF0 = 9216;
constexpr int VOFF1 = 13824;
constexpr int ATTN_SMEM = 18432 * 2;                     // 36864 B
// gemm smem: 3 stages x (A 128x72 + B 128x72) halves; stage = 9216 u32
constexpr int GEMM_SMEM = 3 * 9216 * 4;                  // 110592 B
}

// ---- fp16 mma (fp32 accumulate) ----
__device__ __forceinline__ void mma_f16(float c[4], const uint32_t a[4],
                                        uint32_t b0, uint32_t b1) {
    asm volatile(
        "mma.sync.aligned.m16n8k16.row.col.f32.f16.f16.f32 "
        "{%0,%1,%2,%3},{%4,%5,%6,%7},{%8,%9},{%0,%1,%2,%3};"
        : "+f"(c[0]), "+f"(c[1]), "+f"(c[2]), "+f"(c[3])
        : "r"(a[0]), "r"(a[1]), "r"(a[2]), "r"(a[3]), "r"(b0), "r"(b1));
}
__device__ __forceinline__ uint32_t h2u(float x, float y) {
    __half2 h = __floats2half2_rn(x, y);
    return *reinterpret_cast<uint32_t*>(&h);
}
__device__ __forceinline__ uint32_t ex2h2(float x, float y) {
    uint32_t h = h2u(x, y), r;
    asm("ex2.approx.f16x2 %0, %1;" : "=r"(r) : "r"(h));
    return r;
}
__device__ __forceinline__ float2 h2sumf(uint32_t a, uint32_t b) {
    __half2 s = __hadd2(*reinterpret_cast<__half2*>(&a),
                        *reinterpret_cast<__half2*>(&b));
    return __half22float2(s);
}
__device__ __forceinline__ uint32_t smem_u32p(const void* p) {
    uint32_t a;
    asm("{ .reg .u64 t; cvta.to.shared.u64 t, %1; cvt.u32.u64 %0, t; }" : "=r"(a) : "l"(p));
    return a;
}
#define CP_ASYNC16(dst, src) \
    asm volatile("cp.async.cg.shared.global [%0], [%1], 16;" :: "r"(dst), "l"(src))
#define CP_COMMIT() asm volatile("cp.async.commit_group;")

// ---- scratch (device globals) ----
__device__ __half g_ht[B_ * L_ * C_];        // GN output transposed (b, l, c)
__device__ __half g_q [B_ * NH_ * L_ * 64];  // (bh, l, d), prescaled by QSCALE
__device__ __half g_k [B_ * NH_ * L_ * 64];  // (bh, l, d)
__device__ __half g_v [B_ * NH_ * 64 * L_];  // (bh, d, l)
__device__ __half g_ot[B_ * L_ * C_];        // attention out transposed (b, l, c)
__device__ __half g_wh[768 * 256];           // qkv weights fp16 (Q rows prescaled)
__device__ __half g_wp[256 * 256];           // proj weights fp16
__device__ float  g_bs[768];                 // qkv bias (Q prescaled)
__device__ float  g_mean[B_ * G_];
__device__ float  g_rstd[B_ * G_];

// ---------------------------------------------------------------------------
// GroupNorm stats
// ---------------------------------------------------------------------------
__global__ void gn_stats_kernel(const float* __restrict__ x) {
    const int bg = blockIdx.x;
    const float4* p = reinterpret_cast<const float4*>(x) + (size_t)bg * (CPG_ * L_ / 4);
    float s = 0.f, ss = 0.f;
    for (int i = threadIdx.x; i < CPG_ * L_ / 4; i += blockDim.x) {
        float4 v = p[i];
        s  += v.x + v.y + v.z + v.w;
        ss += v.x * v.x + v.y * v.y + v.z * v.z + v.w * v.w;
    }
#pragma unroll
    for (int o = 16; o > 0; o >>= 1) {
        s  += __shfl_xor_sync(0xffffffffu, s, o);
        ss += __shfl_xor_sync(0xffffffffu, ss, o);
    }
    __shared__ float sh_s[8], sh_ss[8];
    const int w = threadIdx.x >> 5;
    if ((threadIdx.x & 31) == 0) { sh_s[w] = s; sh_ss[w] = ss; }
    __syncthreads();
    if (threadIdx.x == 0) {
        float S = 0.f, SS = 0.f;
#pragma unroll
        for (int i = 0; i < 8; i++) { S += sh_s[i]; SS += sh_ss[i]; }
        const float inv = 1.f / (float)(CPG_ * L_);
        const float mean = S * inv;
        const float var  = SS * inv - mean * mean;
        g_mean[bg] = mean;
        g_rstd[bg] = rsqrtf(var + 1e-5f);
    }
}

// ---------------------------------------------------------------------------
// GroupNorm apply, emitting fp16 h^T as (b, l, c)
// ---------------------------------------------------------------------------
__global__ void gn_apply_t_kernel(const float* __restrict__ x,
                                  const float* __restrict__ w,
                                  const float* __restrict__ bvec) {
    __shared__ __half Ts[64 * 40];
    const int b  = blockIdx.z;
    const int c0 = blockIdx.y * 32;
    const int l0 = blockIdx.x * 64;
    const int tid = threadIdx.x;
#pragma unroll
    for (int i = 0; i < 2; i++) {
        const int e = tid + i * 256;
        const int r = e >> 4;
        const int l4 = (e & 15) * 4;
        const int c = c0 + r;
        const int bg = b * G_ + (c >> 3);
        const float sc = g_rstd[bg] * w[c];
        const float sh = bvec[c] - g_mean[bg] * sc;
        float4 v = *reinterpret_cast<const float4*>(
            x + ((size_t)b * C_ + c) * L_ + l0 + l4);
        Ts[(l4 + 0) * 40 + r] = __float2half_rn(v.x * sc + sh);
        Ts[(l4 + 1) * 40 + r] = __float2half_rn(v.y * sc + sh);
        Ts[(l4 + 2) * 40 + r] = __float2half_rn(v.z * sc + sh);
        Ts[(l4 + 3) * 40 + r] = __float2half_rn(v.w * sc + sh);
    }
    __syncthreads();
    const int r = tid >> 2;
    const int q4 = (tid & 3) * 8;
    *reinterpret_cast<uint4*>(g_ht + ((size_t)b * L_ + l0 + r) * C_ + c0 + q4) =
        *reinterpret_cast<const uint4*>(Ts + r * 40 + q4);
}

// ---------------------------------------------------------------------------
// weight/bias conversion
// ---------------------------------------------------------------------------
__global__ void wconv_kernel(const float* __restrict__ qkvw,
                             const float* __restrict__ projw,
                             const float* __restrict__ qkvb) {
    const int row = blockIdx.x, t = threadIdx.x;
    if (row < 768) {
        const float s = (row < 256) ? QSCALE : 1.f;
        g_wh[row * 256 + t] = __float2half_rn(qkvw[row * 256 + t] * s);
        if (t == 0) g_bs[row] = qkvb[row] * s;
    } else {
        const int r = row - 768;
        g_wp[r * 256 + t] = __float2half_rn(projw[r * 256 + t]);
    }
}

// ---------------------------------------------------------------------------
// QKV GEMM (fp16 mma, 3-stage cp.async ring over 4 k-chunks).
// grid (L/128, 6, B), 256 threads. Epilogue routes Q,K -> (bh,l,d),
// V -> (bh,d,l).
// ---------------------------------------------------------------------------
__global__ void __launch_bounds__(256) qkv_mma_kernel() {
    extern __shared__ __align__(16) char smraw[];
    uint32_t* smu = reinterpret_cast<uint32_t*>(smraw);
    const uint32_t sb = smem_u32p(smraw);
    __half* Csh = reinterpret_cast<__half*>(smraw);
    uint32_t* Csu = reinterpret_cast<uint32_t*>(smraw);

    const int tid = threadIdx.x, wid = tid >> 5, lane = tid & 31;
    const int lg = lane >> 2, lt = lane & 3;
    const int nt = blockIdx.x, mt = blockIdx.y, b = blockIdx.z;
    const int m0 = mt * 128, n0g = nt * 128;
    const int moff = (wid & 3) * 32, noff = (wid >> 2) * 64;
    const __half* wsrc = g_wh;
    const __half* hsrc = g_ht + ((size_t)b * L_ + n0g) * 256;

    auto issueAB = [&](int kc, uint32_t ub /*u32 stage base*/) {
#pragma unroll
        for (int i = 0; i < 4; i++) {
            const int e = tid + i * 256;
            const int r = e >> 3, c8 = (e & 7) * 8;
            CP_ASYNC16(sb + ub * 4 + r * 144 + c8 * 2,
                       wsrc + (size_t)(m0 + r) * 256 + kc * 64 + c8);
            CP_ASYNC16(sb + (ub + 4608) * 4 + r * 144 + c8 * 2,
                       hsrc + (size_t)r * 256 + kc * 64 + c8);
        }
        CP_COMMIT();
    };

    issueAB(0, 0);
    issueAB(1, 9216);

    float oc[2][8][4] = {};
    uint32_t scb = 0, snb = 18432;
    for (int k = 0; k < 4; k++) {
        if (k < 3) asm volatile("cp.async.wait_group 1;" ::: "memory");
        else       asm volatile("cp.async.wait_group 0;" ::: "memory");
        __syncthreads();
        if (k + 2 < 4) issueAB(k + 2, snb);
        const uint32_t* Asu = smu + scb;
        const uint32_t* Bsu = smu + scb + 4608;
#pragma unroll
        for (int kc = 0; kc < 4; kc++) {
            uint32_t a[2][4];
#pragma unroll
            for (int m = 0; m < 2; m++) {
                const int r0 = moff + m * 16 + lg;
                a[m][0] = Asu[r0 * 36 + kc * 8 + lt];
                a[m][1] = Asu[(r0 + 8) * 36 + kc * 8 + lt];
                a[m][2] = Asu[r0 * 36 + kc * 8 + lt + 4];
                a[m][3] = Asu[(r0 + 8) * 36 + kc * 8 + lt + 4];
            }
#pragma unroll
            for (int n = 0; n < 8; n++) {
                const int brow = noff + n * 8 + lg;
                const uint32_t b0 = Bsu[brow * 36 + kc * 8 + lt];
                const uint32_t b1 = Bsu[brow * 36 + kc * 8 + lt + 4];
                mma_f16(oc[0][n], a[0], b0, b1);
                mma_f16(oc[1][n], a[1], b0, b1);
            }
        }
        scb = (scb == 18432) ? 0 : scb + 9216;
        snb = (snb == 18432) ? 0 : snb + 9216;
    }
    __syncthreads();

    const int sel = mt >> 1;
    const int h0 = (mt & 1) * 2;
    float bv[2][2];
#pragma unroll
    for (int m = 0; m < 2; m++) {
        bv[m][0] = g_bs[m0 + moff + m * 16 + lg];
        bv[m][1] = g_bs[m0 + moff + m * 16 + lg + 8];
    }

    if (sel < 2) {
        // transposed stage: Csh[l][m], stride 136
#pragma unroll
        for (int m = 0; m < 2; m++) {
            const int r = moff + m * 16 + lg;
#pragma unroll
            for (int n = 0; n < 8; n++) {
                const int col = noff + n * 8 + 2 * lt;
                Csh[col * 136 + r]           = __float2half_rn(oc[m][n][0] + bv[m][0]);
                Csh[(col + 1) * 136 + r]     = __float2half_rn(oc[m][n][1] + bv[m][0]);
                Csh[col * 136 + r + 8]       = __float2half_rn(oc[m][n][2] + bv[m][1]);
                Csh[(col + 1) * 136 + r + 8] = __float2half_rn(oc[m][n][3] + bv[m][1]);
            }
        }
        __syncthreads();
        __half* dst = (sel == 0 ? g_q : g_k);
#pragma unroll
        for (int i = 0; i < 8; i++) {
            const int e = tid + i * 256;
            const int l = e >> 4;
            const int seg = e & 15;
            const int hd = seg >> 3, q8 = (seg & 7) * 8;
            *reinterpret_cast<uint4*>(
                dst + ((size_t)(b * NH_ + h0 + hd) * L_ + n0g + l) * 64 + q8) =
                *reinterpret_cast<const uint4*>(Csh + l * 136 + hd * 64 + q8);
        }
    } else {
        // natural stage: Csh[m][n], stride 136 (68 u32)
#pragma unroll
        for (int m = 0; m < 2; m++) {
            const int r = moff + m * 16 + lg;
#pragma unroll
            for (int n = 0; n < 8; n++) {
                const int cu = (noff >> 1) + n * 4 + lt;
                Csu[r * 68 + cu]       = h2u(oc[m][n][0] + bv[m][0], oc[m][n][1] + bv[m][0]);
                Csu[(r + 8) * 68 + cu] = h2u(oc[m][n][2] + bv[m][1], oc[m][n][3] + bv[m][1]);
            }
        }
        __syncthreads();
#pragma unroll
        for (int i = 0; i < 8; i++) {
            const int e = tid + i * 256;
            const int r = e >> 4;
            const int c8 = (e & 15) * 8;
            const int hd = r >> 6, d = r & 63;
            *reinterpret_cast<uint4*>(
                g_v + ((size_t)((b * NH_ + h0 + hd) * 64 + d)) * L_ + n0g + c8) =
                *reinterpret_cast<const uint4*>(Csh + r * 136 + c8);
        }
    }
}

// ---------------------------------------------------------------------------
// Flash attention (FA-2 register P). CTA = 128 thr, 128 queries, one bh.
// 64-key tiles, double-buffered cp.async (R9 protocol: issue -> wait -> sync
// -> compute -> sync). Row sums via HADD2 on P fragments (no ones-row).
// log2-domain logits -> ex2.f16x2.
// ---------------------------------------------------------------------------
__global__ void __launch_bounds__(128, 3) attn_kernel(__half* __restrict__ ot) {
    extern __shared__ __align__(16) __half smh[];
    uint32_t* smu = reinterpret_cast<uint32_t*>(smh);
    const uint32_t sb = smem_u32p(smh);

    const int tid = threadIdx.x, wid = tid >> 5, lane = tid & 31;
    const int lg = lane >> 2, lt = lane & 3;
    const int qb = wid * 32;
    const int l0 = blockIdx.x * 128;
    const int bh = blockIdx.y, b = bh >> 2, head = bh & 3;
    const __half* qg = g_q + ((size_t)bh * L_ + l0) * 64;
    const __half* kg = g_k + (size_t)bh * L_ * 64;
    const __half* vg = g_v + (size_t)bh * 64 * L_;

    // ---- stage Q (128 x 64) in K0 region, extract A-fragments ----
#pragma unroll
    for (int i = 0; i < 8; i++) {
        const int e = tid + i * 128;
        const int r = e >> 3, c8 = (e & 7) * 8;
        *reinterpret_cast<uint4*>(smh + r * 72 + c8) =
            *reinterpret_cast<const uint4*>(qg + (size_t)r * 64 + c8);
    }
    __syncthreads();
    uint32_t qa[2][4][4];
#pragma unroll
    for (int m = 0; m < 2; m++) {
        const int r0 = qb + m * 16 + lg;
#pragma unroll
        for (int kc = 0; kc < 4; kc++) {
            qa[m][kc][0] = smu[r0 * 36 + kc * 8 + lt];
            qa[m][kc][1] = smu[(r0 + 8) * 36 + kc * 8 + lt];
            qa[m][kc][2] = smu[r0 * 36 + kc * 8 + lt + 4];
            qa[m][kc][3] = smu[(r0 + 8) * 36 + kc * 8 + lt + 4];
        }
    }
    __syncthreads();   // all warps done reading Q before buffers are reused

    auto issue = [&](int tile, uint32_t koff, uint32_t voff) {
        const __half* ks = kg + (size_t)tile * 64 * 64;
        const __half* vs = vg + tile * 64;
#pragma unroll
        for (int i = 0; i < 4; i++) {
            const int e = tid + i * 128;
            const int r = e >> 3, c8 = (e & 7) * 8;
            CP_ASYNC16(sb + (koff + r * 72 + c8) * 2, ks + (size_t)r * 64 + c8);
            CP_ASYNC16(sb + (voff + r * 72 + c8) * 2, vs + (size_t)r * L_ + c8);
        }
        CP_COMMIT();
    };

    float oc[2][8][4] = {};
    float rs[2][2] = {{0.f, 0.f}, {0.f, 0.f}};
    issue(0, KOFF0, VOFF0);

    for (int it = 0; it < 64; ++it) {
        const int cur = it & 1;
        const uint32_t koff = cur ? KOFF1 : KOFF0;
        const uint32_t voff = cur ? VOFF1 : VOFF0;
        if (it < 63) {
            issue(it + 1, cur ? KOFF0 : KOFF1, cur ? VOFF0 : VOFF1);
            asm volatile("cp.async.wait_group 1;" ::: "memory");
        } else {
            asm volatile("cp.async.wait_group 0;" ::: "memory");
        }
        __syncthreads();
        const uint32_t* Ku = smu + (koff >> 1);
        const uint32_t* Vu = smu + (voff >> 1);

#pragma unroll
        for (int kb = 0; kb < 4; kb++) {
            float ca0[4] = {}, cb0[4] = {}, ca1[4] = {}, cb1[4] = {};
            const int kr0 = kb * 16 + lg, kr1 = kr0 + 8;
#pragma unroll
            for (int kc = 0; kc < 4; kc++) {
                const uint32_t b0 = Ku[kr0 * 36 + kc * 8 + lt];
                const uint32_t b1 = Ku[kr0 * 36 + kc * 8 + lt + 4];
                mma_f16(ca0, qa[0][kc], b0, b1);
                mma_f16(cb0, qa[1][kc], b0, b1);
                const uint32_t d0 = Ku[kr1 * 36 + kc * 8 + lt];
                const uint32_t d1 = Ku[kr1 * 36 + kc * 8 + lt + 4];
                mma_f16(ca1, qa[0][kc], d0, d1);
                mma_f16(cb1, qa[1][kc], d0, d1);
            }
            uint32_t pa0[4] = {ex2h2(ca0[0], ca0[1]), ex2h2(ca0[2], ca0[3]),
                               ex2h2(ca1[0], ca1[1]), ex2h2(ca1[2], ca1[3])};
            uint32_t pa1[4] = {ex2h2(cb0[0], cb0[1]), ex2h2(cb0[2], cb0[3]),
                               ex2h2(cb1[0], cb1[1]), ex2h2(cb1[2], cb1[3])};
            // row sums from the same fp16 P the MMA consumes
            {
                float2 f;
                f = h2sumf(pa0[0], pa0[2]); rs[0][0] += f.x + f.y;
                f = h2sumf(pa0[1], pa0[3]); rs[0][1] += f.x + f.y;
                f = h2sumf(pa1[0], pa1[2]); rs[1][0] += f.x + f.y;
                f = h2sumf(pa1[1], pa1[3]); rs[1][1] += f.x + f.y;
            }
#pragma unroll
            for (int n = 0; n < 8; n++) {
                const int vrow = n * 8 + lg;
                const uint32_t b0 = Vu[vrow * 36 + kb * 8 + lt];
                const uint32_t b1 = Vu[vrow * 36 + kb * 8 + lt + 4];
                mma_f16(oc[0][n], pa0, b0, b1);
                mma_f16(oc[1][n], pa1, b0, b1);
            }
        }
        __syncthreads();
    }

    // ---- quad-reduce row sums, normalize ----
    float inv[2][2];
#pragma unroll
    for (int m = 0; m < 2; m++)
#pragma unroll
        for (int r = 0; r < 2; r++) {
            float v = rs[m][r];
            v += __shfl_xor_sync(0xffffffffu, v, 1);
            v += __shfl_xor_sync(0xffffffffu, v, 2);
            inv[m][r] = 1.f / v;
        }

    // ---- stage O (l, d) fp16 in K0 region, write (b, l, c) rows ----
#pragma unroll
    for (int m = 0; m < 2; m++) {
        const int qrow = qb + m * 16 + lg;
#pragma unroll
        for (int n = 0; n < 8; n++) {
            smu[qrow * 36 + n * 4 + lt] =
                h2u(oc[m][n][0] * inv[m][0], oc[m][n][1] * inv[m][0]);
            smu[(qrow + 8) * 36 + n * 4 + lt] =
                h2u(oc[m][n][2] * inv[m][1], oc[m][n][3] * inv[m][1]);
        }
    }
    __syncthreads();
    __half* otp = ot + ((size_t)b * L_ + l0) * C_ + head * 64;
#pragma unroll
    for (int i = 0; i < 8; i++) {
        const int e = tid + i * 128;
        const int l = e >> 3, c8 = (e & 7) * 8;
        *reinterpret_cast<uint4*>(otp + (size_t)l * C_ + c8) =
            *reinterpret_cast<const uint4*>(smh + l * 72 + c8);
    }
}

// ---------------------------------------------------------------------------
// proj GEMM (fp16 mma, 3-stage cp.async ring) + bias + residual, fp32 out
// ---------------------------------------------------------------------------
__global__ void __launch_bounds__(256) proj_mma_kernel(
    const float* __restrict__ projb, const float* __restrict__ x,
    float* __restrict__ out)
{
    extern __shared__ __align__(16) char smraw[];
    uint32_t* smu = reinterpret_cast<uint32_t*>(smraw);
    const uint32_t sb = smem_u32p(smraw);

    const int tid = threadIdx.x, wid = tid >> 5, lane = tid & 31;
    const int lg = lane >> 2, lt = lane & 3;
    const int nt = blockIdx.x, mt = blockIdx.y, b = blockIdx.z;
    const int m0 = mt * 128, n0g = nt * 128;
    const int moff = (wid & 3) * 32, noff = (wid >> 2) * 64;
    const __half* wsrc = g_wp;
    const __half* osrc = g_ot + ((size_t)b * L_ + n0g) * 256;

    auto issueAB = [&](int kc, uint32_t ub) {
#pragma unroll
        for (int i = 0; i < 4; i++) {
            const int e = tid + i * 256;
            const int r = e >> 3, c8 = (e & 7) * 8;
            CP_ASYNC16(sb + ub * 4 + r * 144 + c8 * 2,
                       wsrc + (size_t)(m0 + r) * 256 + kc * 64 + c8);
            CP_ASYNC16(sb + (ub + 4608) * 4 + r * 144 + c8 * 2,
                       osrc + (size_t)r * 256 + kc * 64 + c8);
        }
        CP_COMMIT();
    };
    issueAB(0, 0);
    issueAB(1, 9216);

    float oc[2][8][4] = {};
    uint32_t scb = 0, snb = 18432;
    for (int k = 0; k < 4; k++) {
        if (k < 3) asm volatile("cp.async.wait_group 1;" ::: "memory");
        else       asm volatile("cp.async.wait_group 0;" ::: "memory");
        __syncthreads();
        if (k + 2 < 4) issueAB(k + 2, snb);
        const uint32_t* Asu = smu + scb;
        const uint32_t* Bsu = smu + scb + 4608;
#pragma unroll
        for (int kc = 0; kc < 4; kc++) {
            uint32_t a[2][4];
#pragma unroll
            for (int m = 0; m < 2; m++) {
                const int r0 = moff + m * 16 + lg;
                a[m][0] = Asu[r0 * 36 + kc * 8 + lt];
                a[m][1] = Asu[(r0 + 8) * 36 + kc * 8 + lt];
                a[m][2] = Asu[r0 * 36 + kc * 8 + lt + 4];
                a[m][3] = Asu[(r0 + 8) * 36 + kc * 8 + lt + 4];
            }
#pragma unroll
            for (int n = 0; n < 8; n++) {
                const int brow = noff + n * 8 + lg;
                const uint32_t b0 = Bsu[brow * 36 + kc * 8 + lt];
                const uint32_t b1 = Bsu[brow * 36 + kc * 8 + lt + 4];
                mma_f16(oc[0][n], a[0], b0, b1);
                mma_f16(oc[1][n], a[1], b0, b1);
            }
        }
        scb = (scb == 18432) ? 0 : scb + 9216;
        snb = (snb == 18432) ? 0 : snb + 9216;
    }
    // direct epilogue: bias + residual + fp32 store
#pragma unroll
    for (int m = 0; m < 2; m++) {
        const int crow = m0 + moff + m * 16 + lg;
        const float b0v = projb[crow], b1v = projb[crow + 8];
        const float* xp0 = x   + ((size_t)b * C_ + crow) * L_;
        float*       op0 = out + ((size_t)b * C_ + crow) * L_;
#pragma unroll
        for (int n = 0; n < 8; n++) {
            const int col = n0g + noff + n * 8 + 2 * lt;
            float2 xr = *reinterpret_cast<const float2*>(xp0 + col);
            *reinterpret_cast<float2*>(op0 + col) =
                make_float2(oc[m][n][0] + b0v + xr.x, oc[m][n][1] + b0v + xr.y);
            float2 xr2 = *reinterpret_cast<const float2*>(xp0 + 8 * L_ + col);
            *reinterpret_cast<float2*>(op0 + 8 * L_ + col) =
                make_float2(oc[m][n][2] + b1v + xr2.x, oc[m][n][3] + b1v + xr2.y);
        }
    }
}

// ---------------------------------------------------------------------------
// Host launcher
// ---------------------------------------------------------------------------
extern "C" void kernel_launch(void* const* d_in, const int* in_sizes, int n_in,
                              void* d_out, int out_size) {
    (void)in_sizes; (void)n_in; (void)out_size;
    const float* x      = (const float*)d_in[0];
    const float* gn_w   = (const float*)d_in[1];
    const float* gn_b   = (const float*)d_in[2];
    const float* qkv_w  = (const float*)d_in[3];
    const float* qkv_b  = (const float*)d_in[4];
    const float* proj_w = (const float*)d_in[5];
    const float* proj_b = (const float*)d_in[6];
    float* out = (float*)d_out;

    void* pot;
    cudaGetSymbolAddress(&pot, g_ot);
    __half* ot = (__half*)pot;

    // 1) GroupNorm -> fp16 transposed h
    gn_stats_kernel<<<B_ * G_, 256>>>(x);
    gn_apply_t_kernel<<<dim3(L_ / 64, C_ / 32, B_), 256>>>(x, gn_w, gn_b);

    // weight conversion
    wconv_kernel<<<1024, 256>>>(qkv_w, proj_w, qkv_b);

    // 2) QKV mma GEMM -> fp16 Q/K/V in attention layouts
    cudaFuncSetAttribute(qkv_mma_kernel,
                         cudaFuncAttributeMaxDynamicSharedMemorySize, GEMM_SMEM);
    qkv_mma_kernel<<<dim3(L_ / 128, 6, B_), 256, GEMM_SMEM>>>();

    // 3) Attention
    cudaFuncSetAttribute(attn_kernel,
                         cudaFuncAttributeMaxDynamicSharedMemorySize, ATTN_SMEM);
    attn_kernel<<<dim3(L_ / 128, B_ * NH_), 128, ATTN_SMEM>>>(ot);

    // 4) proj mma GEMM + bias + residual
    cudaFuncSetAttribute(proj_mma_kernel,
                         cudaFuncAttributeMaxDynamicSharedMemorySize, GEMM_SMEM);
    proj_mma_kernel<<<dim3(L_ / 128, 2, B_), 256, GEMM_SMEM>>>(proj_b, x, out);
}

// round 13
// speedup vs baseline: 1.0162x; 1.0013x over previous
#include <cuda_runtime.h>
#include <cuda_fp16.h>
#include <cstdint>

// ---------------------------------------------------------------------------
// AttentionBlock, fully tensor-core (fp16 mma.m16n8k16, fp32 accum):
//   GroupNorm (fp16 transposed) -> QKV mma GEMM (3-stage cp.async ring)
//   -> FA-2 flash attention (register P, ex2.f16x2, ones-row row sums,
//      R9 double-buffer protocol, 64 queries/CTA) -> proj mma GEMM + residual.
// B=4, C=256, L=4096, 4 heads, d=64.
// ---------------------------------------------------------------------------

namespace {
constexpr int B_  = 4;
constexpr int C_  = 256;
constexpr int L_  = 4096;
constexpr int G_  = 32;
constexpr int NH_ = 4;
constexpr int CPG_ = C_ / G_;
constexpr float QSCALE = 0.125f * 1.4426950408889634f;   // d^-0.5 * log2(e)
// attention smem (halves): K tiles 64x72, V tiles 72x72 (rows 64..71 const)
constexpr int KOFF0 = 0;
constexpr int KOFF1 = 4608;
constexpr int VOFF0 = 9216;
constexpr int VOFF1 = 14400;
constexpr int ATTN_SMEM = 19584 * 2;                     // 39168 B
// gemm smem: 3 stages x (A 128x72 + B 128x72) halves; stage = 9216 u32
constexpr int GEMM_SMEM = 3 * 9216 * 4;                  // 110592 B
}

// ---- fp16 mma (fp32 accumulate) ----
__device__ __forceinline__ void mma_f16(float c[4], const uint32_t a[4],
                                        uint32_t b0, uint32_t b1) {
    asm volatile(
        "mma.sync.aligned.m16n8k16.row.col.f32.f16.f16.f32 "
        "{%0,%1,%2,%3},{%4,%5,%6,%7},{%8,%9},{%0,%1,%2,%3};"
        : "+f"(c[0]), "+f"(c[1]), "+f"(c[2]), "+f"(c[3])
        : "r"(a[0]), "r"(a[1]), "r"(a[2]), "r"(a[3]), "r"(b0), "r"(b1));
}
__device__ __forceinline__ uint32_t h2u(float x, float y) {
    __half2 h = __floats2half2_rn(x, y);
    return *reinterpret_cast<uint32_t*>(&h);
}
__device__ __forceinline__ uint32_t ex2h2(float x, float y) {
    uint32_t h = h2u(x, y), r;
    asm("ex2.approx.f16x2 %0, %1;" : "=r"(r) : "r"(h));
    return r;
}
__device__ __forceinline__ uint32_t smem_u32p(const void* p) {
    uint32_t a;
    asm("{ .reg .u64 t; cvta.to.shared.u64 t, %1; cvt.u32.u64 %0, t; }" : "=r"(a) : "l"(p));
    return a;
}
#define CP_ASYNC16(dst, src) \
    asm volatile("cp.async.cg.shared.global [%0], [%1], 16;" :: "r"(dst), "l"(src))
#define CP_COMMIT() asm volatile("cp.async.commit_group;")

// ---- scratch (device globals) ----
__device__ __half g_ht[B_ * L_ * C_];        // GN output transposed (b, l, c)
__device__ __half g_q [B_ * NH_ * L_ * 64];  // (bh, l, d), prescaled by QSCALE
__device__ __half g_k [B_ * NH_ * L_ * 64];  // (bh, l, d)
__device__ __half g_v [B_ * NH_ * 64 * L_];  // (bh, d, l)
__device__ __half g_ot[B_ * L_ * C_];        // attention out transposed (b, l, c)
__device__ __half g_wh[768 * 256];           // qkv weights fp16 (Q rows prescaled)
__device__ __half g_wp[256 * 256];           // proj weights fp16
__device__ float  g_bs[768];                 // qkv bias (Q prescaled)
__device__ float  g_mean[B_ * G_];
__device__ float  g_rstd[B_ * G_];

// ---------------------------------------------------------------------------
// GroupNorm stats
// ---------------------------------------------------------------------------
__global__ void gn_stats_kernel(const float* __restrict__ x) {
    const int bg = blockIdx.x;
    const float4* p = reinterpret_cast<const float4*>(x) + (size_t)bg * (CPG_ * L_ / 4);
    float s = 0.f, ss = 0.f;
    for (int i = threadIdx.x; i < CPG_ * L_ / 4; i += blockDim.x) {
        float4 v = p[i];
        s  += v.x + v.y + v.z + v.w;
        ss += v.x * v.x + v.y * v.y + v.z * v.z + v.w * v.w;
    }
#pragma unroll
    for (int o = 16; o > 0; o >>= 1) {
        s  += __shfl_xor_sync(0xffffffffu, s, o);
        ss += __shfl_xor_sync(0xffffffffu, ss, o);
    }
    __shared__ float sh_s[8], sh_ss[8];
    const int w = threadIdx.x >> 5;
    if ((threadIdx.x & 31) == 0) { sh_s[w] = s; sh_ss[w] = ss; }
    __syncthreads();
    if (threadIdx.x == 0) {
        float S = 0.f, SS = 0.f;
#pragma unroll
        for (int i = 0; i < 8; i++) { S += sh_s[i]; SS += sh_ss[i]; }
        const float inv = 1.f / (float)(CPG_ * L_);
        const float mean = S * inv;
        const float var  = SS * inv - mean * mean;
        g_mean[bg] = mean;
        g_rstd[bg] = rsqrtf(var + 1e-5f);
    }
}

// ---------------------------------------------------------------------------
// GroupNorm apply, emitting fp16 h^T as (b, l, c)
// ---------------------------------------------------------------------------
__global__ void gn_apply_t_kernel(const float* __restrict__ x,
                                  const float* __restrict__ w,
                                  const float* __restrict__ bvec) {
    __shared__ __half Ts[64 * 40];
    const int b  = blockIdx.z;
    const int c0 = blockIdx.y * 32;
    const int l0 = blockIdx.x * 64;
    const int tid = threadIdx.x;
#pragma unroll
    for (int i = 0; i < 2; i++) {
        const int e = tid + i * 256;
        const int r = e >> 4;
        const int l4 = (e & 15) * 4;
        const int c = c0 + r;
        const int bg = b * G_ + (c >> 3);
        const float sc = g_rstd[bg] * w[c];
        const float sh = bvec[c] - g_mean[bg] * sc;
        float4 v = *reinterpret_cast<const float4*>(
            x + ((size_t)b * C_ + c) * L_ + l0 + l4);
        Ts[(l4 + 0) * 40 + r] = __float2half_rn(v.x * sc + sh);
        Ts[(l4 + 1) * 40 + r] = __float2half_rn(v.y * sc + sh);
        Ts[(l4 + 2) * 40 + r] = __float2half_rn(v.z * sc + sh);
        Ts[(l4 + 3) * 40 + r] = __float2half_rn(v.w * sc + sh);
    }
    __syncthreads();
    const int r = tid >> 2;
    const int q4 = (tid & 3) * 8;
    *reinterpret_cast<uint4*>(g_ht + ((size_t)b * L_ + l0 + r) * C_ + c0 + q4) =
        *reinterpret_cast<const uint4*>(Ts + r * 40 + q4);
}

// ---------------------------------------------------------------------------
// weight/bias conversion
// ---------------------------------------------------------------------------
__global__ void wconv_kernel(const float* __restrict__ qkvw,
                             const float* __restrict__ projw,
                             const float* __restrict__ qkvb) {
    const int row = blockIdx.x, t = threadIdx.x;
    if (row < 768) {
        const float s = (row < 256) ? QSCALE : 1.f;
        g_wh[row * 256 + t] = __float2half_rn(qkvw[row * 256 + t] * s);
        if (t == 0) g_bs[row] = qkvb[row] * s;
    } else {
        const int r = row - 768;
        g_wp[r * 256 + t] = __float2half_rn(projw[r * 256 + t]);
    }
}

// ---------------------------------------------------------------------------
// QKV GEMM (fp16 mma, 3-stage cp.async ring over 4 k-chunks).
// grid (L/128, 6, B), 256 threads. Epilogue routes Q,K -> (bh,l,d),
// V -> (bh,d,l).
// ---------------------------------------------------------------------------
__global__ void __launch_bounds__(256) qkv_mma_kernel() {
    extern __shared__ __align__(16) char smraw[];
    uint32_t* smu = reinterpret_cast<uint32_t*>(smraw);
    const uint32_t sb = smem_u32p(smraw);
    __half* Csh = reinterpret_cast<__half*>(smraw);
    uint32_t* Csu = reinterpret_cast<uint32_t*>(smraw);

    const int tid = threadIdx.x, wid = tid >> 5, lane = tid & 31;
    const int lg = lane >> 2, lt = lane & 3;
    const int nt = blockIdx.x, mt = blockIdx.y, b = blockIdx.z;
    const int m0 = mt * 128, n0g = nt * 128;
    const int moff = (wid & 3) * 32, noff = (wid >> 2) * 64;
    const __half* wsrc = g_wh;
    const __half* hsrc = g_ht + ((size_t)b * L_ + n0g) * 256;

    auto issueAB = [&](int kc, uint32_t ub /*u32 stage base*/) {
#pragma unroll
        for (int i = 0; i < 4; i++) {
            const int e = tid + i * 256;
            const int r = e >> 3, c8 = (e & 7) * 8;
            CP_ASYNC16(sb + ub * 4 + r * 144 + c8 * 2,
                       wsrc + (size_t)(m0 + r) * 256 + kc * 64 + c8);
            CP_ASYNC16(sb + (ub + 4608) * 4 + r * 144 + c8 * 2,
                       hsrc + (size_t)r * 256 + kc * 64 + c8);
        }
        CP_COMMIT();
    };

    issueAB(0, 0);
    issueAB(1, 9216);

    float oc[2][8][4] = {};
    uint32_t scb = 0, snb = 18432;
    for (int k = 0; k < 4; k++) {
        if (k < 3) asm volatile("cp.async.wait_group 1;" ::: "memory");
        else       asm volatile("cp.async.wait_group 0;" ::: "memory");
        __syncthreads();
        if (k + 2 < 4) issueAB(k + 2, snb);
        const uint32_t* Asu = smu + scb;
        const uint32_t* Bsu = smu + scb + 4608;
#pragma unroll
        for (int kc = 0; kc < 4; kc++) {
            uint32_t a[2][4];
#pragma unroll
            for (int m = 0; m < 2; m++) {
                const int r0 = moff + m * 16 + lg;
                a[m][0] = Asu[r0 * 36 + kc * 8 + lt];
                a[m][1] = Asu[(r0 + 8) * 36 + kc * 8 + lt];
                a[m][2] = Asu[r0 * 36 + kc * 8 + lt + 4];
                a[m][3] = Asu[(r0 + 8) * 36 + kc * 8 + lt + 4];
            }
#pragma unroll
            for (int n = 0; n < 8; n++) {
                const int brow = noff + n * 8 + lg;
                const uint32_t b0 = Bsu[brow * 36 + kc * 8 + lt];
                const uint32_t b1 = Bsu[brow * 36 + kc * 8 + lt + 4];
                mma_f16(oc[0][n], a[0], b0, b1);
                mma_f16(oc[1][n], a[1], b0, b1);
            }
        }
        scb = (scb == 18432) ? 0 : scb + 9216;
        snb = (snb == 18432) ? 0 : snb + 9216;
    }
    __syncthreads();

    const int sel = mt >> 1;
    const int h0 = (mt & 1) * 2;
    float bv[2][2];
#pragma unroll
    for (int m = 0; m < 2; m++) {
        bv[m][0] = g_bs[m0 + moff + m * 16 + lg];
        bv[m][1] = g_bs[m0 + moff + m * 16 + lg + 8];
    }

    if (sel < 2) {
        // transposed stage: Csh[l][m], stride 136
#pragma unroll
        for (int m = 0; m < 2; m++) {
            const int r = moff + m * 16 + lg;
#pragma unroll
            for (int n = 0; n < 8; n++) {
                const int col = noff + n * 8 + 2 * lt;
                Csh[col * 136 + r]           = __float2half_rn(oc[m][n][0] + bv[m][0]);
                Csh[(col + 1) * 136 + r]     = __float2half_rn(oc[m][n][1] + bv[m][0]);
                Csh[col * 136 + r + 8]       = __float2half_rn(oc[m][n][2] + bv[m][1]);
                Csh[(col + 1) * 136 + r + 8] = __float2half_rn(oc[m][n][3] + bv[m][1]);
            }
        }
        __syncthreads();
        __half* dst = (sel == 0 ? g_q : g_k);
#pragma unroll
        for (int i = 0; i < 8; i++) {
            const int e = tid + i * 256;
            const int l = e >> 4;
            const int seg = e & 15;
            const int hd = seg >> 3, q8 = (seg & 7) * 8;
            *reinterpret_cast<uint4*>(
                dst + ((size_t)(b * NH_ + h0 + hd) * L_ + n0g + l) * 64 + q8) =
                *reinterpret_cast<const uint4*>(Csh + l * 136 + hd * 64 + q8);
        }
    } else {
        // natural stage: Csh[m][n], stride 136 (68 u32)
#pragma unroll
        for (int m = 0; m < 2; m++) {
            const int r = moff + m * 16 + lg;
#pragma unroll
            for (int n = 0; n < 8; n++) {
                const int cu = (noff >> 1) + n * 4 + lt;
                Csu[r * 68 + cu]       = h2u(oc[m][n][0] + bv[m][0], oc[m][n][1] + bv[m][0]);
                Csu[(r + 8) * 68 + cu] = h2u(oc[m][n][2] + bv[m][1], oc[m][n][3] + bv[m][1]);
            }
        }
        __syncthreads();
#pragma unroll
        for (int i = 0; i < 8; i++) {
            const int e = tid + i * 256;
            const int r = e >> 4;
            const int c8 = (e & 15) * 8;
            const int hd = r >> 6, d = r & 63;
            *reinterpret_cast<uint4*>(
                g_v + ((size_t)((b * NH_ + h0 + hd) * 64 + d)) * L_ + n0g + c8) =
                *reinterpret_cast<const uint4*>(Csh + r * 136 + c8);
        }
    }
}

// ---------------------------------------------------------------------------
// Flash attention (FA-2 register P). CTA = 128 thr, 64 queries (16/warp),
// one bh. 64-key tiles, double-buffered cp.async (R9 protocol). Row sums via
// ones-row (V row 64 = 1.0). log2-domain logits -> ex2.f16x2.
// ---------------------------------------------------------------------------
__global__ void __launch_bounds__(128, 4) attn_kernel(__half* __restrict__ ot) {
    extern __shared__ __align__(16) __half smh[];
    uint32_t* smu = reinterpret_cast<uint32_t*>(smh);
    const uint32_t sb = smem_u32p(smh);

    const int tid = threadIdx.x, wid = tid >> 5, lane = tid & 31;
    const int lg = lane >> 2, lt = lane & 3;
    const int qb = wid * 16;          // warp's query base (local, 16 q/warp)
    const int l0 = blockIdx.x * 64;
    const int bh = blockIdx.y, b = bh >> 2, head = bh & 3;
    const __half* qg = g_q + ((size_t)bh * L_ + l0) * 64;
    const __half* kg = g_k + (size_t)bh * L_ * 64;
    const __half* vg = g_v + (size_t)bh * 64 * L_;

    // const rows 64..71 of both V buffers: row 64 = 1.0 (ones-row), rest 0
    for (int e = tid; e < 576; e += 128) {
        const int buf = e / 288, rem = e % 288;
        const int row = 64 + rem / 36, c = rem % 36;
        smu[((buf ? VOFF1 : VOFF0) >> 1) + row * 36 + c] =
            (row == 64) ? 0x3C003C00u : 0u;
    }
    // stage Q (64 x 64 halves) in K0 region, extract A-fragments
#pragma unroll
    for (int i = 0; i < 4; i++) {
        const int e = tid + i * 128;      // 0..511
        const int r = e >> 3, c8 = (e & 7) * 8;
        *reinterpret_cast<uint4*>(smh + r * 72 + c8) =
            *reinterpret_cast<const uint4*>(qg + (size_t)r * 64 + c8);
    }
    __syncthreads();
    uint32_t qa[4][4];
    {
        const int r0 = qb + lg;
#pragma unroll
        for (int kc = 0; kc < 4; kc++) {
            qa[kc][0] = smu[r0 * 36 + kc * 8 + lt];
            qa[kc][1] = smu[(r0 + 8) * 36 + kc * 8 + lt];
            qa[kc][2] = smu[r0 * 36 + kc * 8 + lt + 4];
            qa[kc][3] = smu[(r0 + 8) * 36 + kc * 8 + lt + 4];
        }
    }
    __syncthreads();   // Q reads complete before K0 is reused by cp.async

    auto issue = [&](int tile, uint32_t koff, uint32_t voff) {
        const __half* ks = kg + (size_t)tile * 64 * 64;
        const __half* vs = vg + tile * 64;
#pragma unroll
        for (int i = 0; i < 4; i++) {
            const int e = tid + i * 128;
            const int r = e >> 3, c8 = (e & 7) * 8;
            CP_ASYNC16(sb + (koff + r * 72 + c8) * 2, ks + (size_t)r * 64 + c8);
            CP_ASYNC16(sb + (voff + r * 72 + c8) * 2, vs + (size_t)r * L_ + c8);
        }
        CP_COMMIT();
    };

    float oc[9][4] = {};
    issue(0, KOFF0, VOFF0);

    for (int it = 0; it < 64; ++it) {
        const int cur = it & 1;
        const uint32_t koff = cur ? KOFF1 : KOFF0;
        const uint32_t voff = cur ? VOFF1 : VOFF0;
        if (it < 63) {
            issue(it + 1, cur ? KOFF0 : KOFF1, cur ? VOFF0 : VOFF1);
            asm volatile("cp.async.wait_group 1;" ::: "memory");
        } else {
            asm volatile("cp.async.wait_group 0;" ::: "memory");
        }
        __syncthreads();
        const uint32_t* Ku = smu + (koff >> 1);
        const uint32_t* Vu = smu + (voff >> 1);

#pragma unroll
        for (int kb = 0; kb < 4; kb++) {
            float ca0[4] = {}, ca1[4] = {};
            const int kr0 = kb * 16 + lg, kr1 = kr0 + 8;
#pragma unroll
            for (int kc = 0; kc < 4; kc++) {
                mma_f16(ca0, qa[kc], Ku[kr0 * 36 + kc * 8 + lt],
                                     Ku[kr0 * 36 + kc * 8 + lt + 4]);
                mma_f16(ca1, qa[kc], Ku[kr1 * 36 + kc * 8 + lt],
                                     Ku[kr1 * 36 + kc * 8 + lt + 4]);
            }
            // exp2 -> PV A-fragment (FA-2 register pipeline)
            uint32_t pa[4] = {ex2h2(ca0[0], ca0[1]), ex2h2(ca0[2], ca0[3]),
                              ex2h2(ca1[0], ca1[1]), ex2h2(ca1[2], ca1[3])};
            // O += P.V^T  (col 64 = ones-row -> row sums accumulate in oc[8])
#pragma unroll
            for (int n = 0; n < 9; n++) {
                const int vrow = n * 8 + lg;
                mma_f16(oc[n], pa, Vu[vrow * 36 + kb * 8 + lt],
                                   Vu[vrow * 36 + kb * 8 + lt + 4]);
            }
        }
        __syncthreads();
    }

    // row sums live in O column 64 at lt==0; broadcast across quad
    const float r0 = __shfl_sync(0xffffffffu, oc[8][0], lane & ~3);
    const float r1 = __shfl_sync(0xffffffffu, oc[8][2], lane & ~3);
    const float inv0 = 1.f / r0, inv1 = 1.f / r1;

    // stage O (l, d) fp16 in K0 region, write (b, l, c) rows
    const int qrow = qb + lg;
#pragma unroll
    for (int n = 0; n < 8; n++) {
        smu[qrow * 36 + n * 4 + lt] =
            h2u(oc[n][0] * inv0, oc[n][1] * inv0);
        smu[(qrow + 8) * 36 + n * 4 + lt] =
            h2u(oc[n][2] * inv1, oc[n][3] * inv1);
    }
    __syncthreads();
    __half* otp = ot + ((size_t)b * L_ + l0) * C_ + head * 64;
#pragma unroll
    for (int i = 0; i < 4; i++) {
        const int e = tid + i * 128;
        const int l = e >> 3, c8 = (e & 7) * 8;
        *reinterpret_cast<uint4*>(otp + (size_t)l * C_ + c8) =
            *reinterpret_cast<const uint4*>(smh + l * 72 + c8);
    }
}

// ---------------------------------------------------------------------------
// proj GEMM (fp16 mma, 3-stage cp.async ring) + bias + residual, fp32 out
// ---------------------------------------------------------------------------
__global__ void __launch_bounds__(256) proj_mma_kernel(
    const float* __restrict__ projb, const float* __restrict__ x,
    float* __restrict__ out)
{
    extern __shared__ __align__(16) char smraw[];
    uint32_t* smu = reinterpret_cast<uint32_t*>(smraw);
    const uint32_t sb = smem_u32p(smraw);

    const int tid = threadIdx.x, wid = tid >> 5, lane = tid & 31;
    const int lg = lane >> 2, lt = lane & 3;
    const int nt = blockIdx.x, mt = blockIdx.y, b = blockIdx.z;
    const int m0 = mt * 128, n0g = nt * 128;
    const int moff = (wid & 3) * 32, noff = (wid >> 2) * 64;
    const __half* wsrc = g_wp;
    const __half* osrc = g_ot + ((size_t)b * L_ + n0g) * 256;

    auto issueAB = [&](int kc, uint32_t ub) {
#pragma unroll
        for (int i = 0; i < 4; i++) {
            const int e = tid + i * 256;
            const int r = e >> 3, c8 = (e & 7) * 8;
            CP_ASYNC16(sb + ub * 4 + r * 144 + c8 * 2,
                       wsrc + (size_t)(m0 + r) * 256 + kc * 64 + c8);
            CP_ASYNC16(sb + (ub + 4608) * 4 + r * 144 + c8 * 2,
                       osrc + (size_t)r * 256 + kc * 64 + c8);
        }
        CP_COMMIT();
    };
    issueAB(0, 0);
    issueAB(1, 9216);

    float oc[2][8][4] = {};
    uint32_t scb = 0, snb = 18432;
    for (int k = 0; k < 4; k++) {
        if (k < 3) asm volatile("cp.async.wait_group 1;" ::: "memory");
        else       asm volatile("cp.async.wait_group 0;" ::: "memory");
        __syncthreads();
        if (k + 2 < 4) issueAB(k + 2, snb);
        const uint32_t* Asu = smu + scb;
        const uint32_t* Bsu = smu + scb + 4608;
#pragma unroll
        for (int kc = 0; kc < 4; kc++) {
            uint32_t a[2][4];
#pragma unroll
            for (int m = 0; m < 2; m++) {
                const int r0 = moff + m * 16 + lg;
                a[m][0] = Asu[r0 * 36 + kc * 8 + lt];
                a[m][1] = Asu[(r0 + 8) * 36 + kc * 8 + lt];
                a[m][2] = Asu[r0 * 36 + kc * 8 + lt + 4];
                a[m][3] = Asu[(r0 + 8) * 36 + kc * 8 + lt + 4];
            }
#pragma unroll
            for (int n = 0; n < 8; n++) {
                const int brow = noff + n * 8 + lg;
                const uint32_t b0 = Bsu[brow * 36 + kc * 8 + lt];
                const uint32_t b1 = Bsu[brow * 36 + kc * 8 + lt + 4];
                mma_f16(oc[0][n], a[0], b0, b1);
                mma_f16(oc[1][n], a[1], b0, b1);
            }
        }
        scb = (scb == 18432) ? 0 : scb + 9216;
        snb = (snb == 18432) ? 0 : snb + 9216;
    }
    // direct epilogue: bias + residual + fp32 store
#pragma unroll
    for (int m = 0; m < 2; m++) {
        const int crow = m0 + moff + m * 16 + lg;
        const float b0v = projb[crow], b1v = projb[crow + 8];
        const float* xp0 = x   + ((size_t)b * C_ + crow) * L_;
        float*       op0 = out + ((size_t)b * C_ + crow) * L_;
#pragma unroll
        for (int n = 0; n < 8; n++) {
            const int col = n0g + noff + n * 8 + 2 * lt;
            float2 xr = *reinterpret_cast<const float2*>(xp0 + col);
            *reinterpret_cast<float2*>(op0 + col) =
                make_float2(oc[m][n][0] + b0v + xr.x, oc[m][n][1] + b0v + xr.y);
            float2 xr2 = *reinterpret_cast<const float2*>(xp0 + 8 * L_ + col);
            *reinterpret_cast<float2*>(op0 + 8 * L_ + col) =
                make_float2(oc[m][n][2] + b1v + xr2.x, oc[m][n][3] + b1v + xr2.y);
        }
    }
}

// ---------------------------------------------------------------------------
// Host launcher
// ---------------------------------------------------------------------------
extern "C" void kernel_launch(void* const* d_in, const int* in_sizes, int n_in,
                              void* d_out, int out_size) {
    (void)in_sizes; (void)n_in; (void)out_size;
    const float* x      = (const float*)d_in[0];
    const float* gn_w   = (const float*)d_in[1];
    const float* gn_b   = (const float*)d_in[2];
    const float* qkv_w  = (const float*)d_in[3];
    const float* qkv_b  = (const float*)d_in[4];
    const float* proj_w = (const float*)d_in[5];
    const float* proj_b = (const float*)d_in[6];
    float* out = (float*)d_out;

    void* pot;
    cudaGetSymbolAddress(&pot, g_ot);
    __half* ot = (__half*)pot;

    // 1) GroupNorm -> fp16 transposed h
    gn_stats_kernel<<<B_ * G_, 256>>>(x);
    gn_apply_t_kernel<<<dim3(L_ / 64, C_ / 32, B_), 256>>>(x, gn_w, gn_b);

    // weight conversion
    wconv_kernel<<<1024, 256>>>(qkv_w, proj_w, qkv_b);

    // 2) QKV mma GEMM -> fp16 Q/K/V in attention layouts
    cudaFuncSetAttribute(qkv_mma_kernel,
                         cudaFuncAttributeMaxDynamicSharedMemorySize, GEMM_SMEM);
    qkv_mma_kernel<<<dim3(L_ / 128, 6, B_), 256, GEMM_SMEM>>>();

    // 3) Attention (64 queries/CTA, grid 1024)
    cudaFuncSetAttribute(attn_kernel,
                         cudaFuncAttributeMaxDynamicSharedMemorySize, ATTN_SMEM);
    attn_kernel<<<dim3(L_ / 64, B_ * NH_), 128, ATTN_SMEM>>>(ot);

    // 4) proj mma GEMM + bias + residual
    cudaFuncSetAttribute(proj_mma_kernel,
                         cudaFuncAttributeMaxDynamicSharedMemorySize, GEMM_SMEM);
    proj_mma_kernel<<<dim3(L_ / 128, 2, B_), 256, GEMM_SMEM>>>(proj_b, x, out);
}

// round 14
// speedup vs baseline: 1.1055x; 1.0878x over previous
#include <cuda_runtime.h>
#include <cuda_fp16.h>
#include <cstdint>

// ---------------------------------------------------------------------------
// AttentionBlock, fully tensor-core (fp16 mma.m16n8k16, fp32 accum):
//   GroupNorm (fp16 transposed) -> QKV mma GEMM (3-stage cp.async ring)
//   -> FA-2 flash attention (R9 config: 128 q/CTA, register P, ex2.f16x2,
//      ones-row row sums, double-buffered cp.async) -> proj mma GEMM + resid.
// B=4, C=256, L=4096, 4 heads, d=64.
// ---------------------------------------------------------------------------

namespace {
constexpr int B_  = 4;
constexpr int C_  = 256;
constexpr int L_  = 4096;
constexpr int G_  = 32;
constexpr int NH_ = 4;
constexpr int CPG_ = C_ / G_;
constexpr float QSCALE = 0.125f * 1.4426950408889634f;   // d^-0.5 * log2(e)
// attention smem offsets (in halves): K 64x72 tiles, V 72x72 tiles
constexpr int KOFF0 = 0;
constexpr int KOFF1 = 4608;
constexpr int VOFF0 = 9216;
constexpr int VOFF1 = 14400;
constexpr int ATTN_SMEM_H = 19584;                       // halves -> 39168 B
// qkv gemm smem: 3 stages x (A 128x72 + B 128x72) halves; stage = 9216 u32
constexpr int GEMM_SMEM = 3 * 9216 * 4;                  // 110592 B
}

// ---- fp16 mma (fp32 accumulate) ----
__device__ __forceinline__ void mma_f16(float c[4], const uint32_t a[4],
                                        uint32_t b0, uint32_t b1) {
    asm volatile(
        "mma.sync.aligned.m16n8k16.row.col.f32.f16.f16.f32 "
        "{%0,%1,%2,%3},{%4,%5,%6,%7},{%8,%9},{%0,%1,%2,%3};"
        : "+f"(c[0]), "+f"(c[1]), "+f"(c[2]), "+f"(c[3])
        : "r"(a[0]), "r"(a[1]), "r"(a[2]), "r"(a[3]), "r"(b0), "r"(b1));
}
__device__ __forceinline__ uint32_t h2u(float x, float y) {
    __half2 h = __floats2half2_rn(x, y);
    return *reinterpret_cast<uint32_t*>(&h);
}
__device__ __forceinline__ uint32_t ex2h2(float x, float y) {
    uint32_t h = h2u(x, y), r;
    asm("ex2.approx.f16x2 %0, %1;" : "=r"(r) : "r"(h));
    return r;
}
__device__ __forceinline__ uint32_t smem_u32p(const void* p) {
    uint32_t a;
    asm("{ .reg .u64 t; cvta.to.shared.u64 t, %1; cvt.u32.u64 %0, t; }" : "=r"(a) : "l"(p));
    return a;
}
#define CP_ASYNC16(dst, src) \
    asm volatile("cp.async.cg.shared.global [%0], [%1], 16;" :: "r"(dst), "l"(src))
#define CP_COMMIT() asm volatile("cp.async.commit_group;")

// ---- scratch (device globals) ----
__device__ __half g_ht[B_ * L_ * C_];        // GN output transposed (b, l, c)
__device__ __half g_q [B_ * NH_ * L_ * 64];  // (bh, l, d), prescaled by QSCALE
__device__ __half g_k [B_ * NH_ * L_ * 64];  // (bh, l, d)
__device__ __half g_v [B_ * NH_ * 64 * L_];  // (bh, d, l)
__device__ __half g_ot[B_ * L_ * C_];        // attention out transposed (b, l, c)
__device__ __half g_wh[768 * 256];           // qkv weights fp16 (Q rows prescaled)
__device__ __half g_wp[256 * 256];           // proj weights fp16
__device__ float  g_bs[768];                 // qkv bias (Q prescaled)
__device__ float  g_mean[B_ * G_];
__device__ float  g_rstd[B_ * G_];

// ---------------------------------------------------------------------------
// GroupNorm stats
// ---------------------------------------------------------------------------
__global__ void gn_stats_kernel(const float* __restrict__ x) {
    const int bg = blockIdx.x;
    const float4* p = reinterpret_cast<const float4*>(x) + (size_t)bg * (CPG_ * L_ / 4);
    float s = 0.f, ss = 0.f;
    for (int i = threadIdx.x; i < CPG_ * L_ / 4; i += blockDim.x) {
        float4 v = p[i];
        s  += v.x + v.y + v.z + v.w;
        ss += v.x * v.x + v.y * v.y + v.z * v.z + v.w * v.w;
    }
#pragma unroll
    for (int o = 16; o > 0; o >>= 1) {
        s  += __shfl_xor_sync(0xffffffffu, s, o);
        ss += __shfl_xor_sync(0xffffffffu, ss, o);
    }
    __shared__ float sh_s[8], sh_ss[8];
    const int w = threadIdx.x >> 5;
    if ((threadIdx.x & 31) == 0) { sh_s[w] = s; sh_ss[w] = ss; }
    __syncthreads();
    if (threadIdx.x == 0) {
        float S = 0.f, SS = 0.f;
#pragma unroll
        for (int i = 0; i < 8; i++) { S += sh_s[i]; SS += sh_ss[i]; }
        const float inv = 1.f / (float)(CPG_ * L_);
        const float mean = S * inv;
        const float var  = SS * inv - mean * mean;
        g_mean[bg] = mean;
        g_rstd[bg] = rsqrtf(var + 1e-5f);
    }
}

// ---------------------------------------------------------------------------
// GroupNorm apply, emitting fp16 h^T as (b, l, c)
// ---------------------------------------------------------------------------
__global__ void gn_apply_t_kernel(const float* __restrict__ x,
                                  const float* __restrict__ w,
                                  const float* __restrict__ bvec) {
    __shared__ __half Ts[64 * 40];
    const int b  = blockIdx.z;
    const int c0 = blockIdx.y * 32;
    const int l0 = blockIdx.x * 64;
    const int tid = threadIdx.x;
#pragma unroll
    for (int i = 0; i < 2; i++) {
        const int e = tid + i * 256;
        const int r = e >> 4;
        const int l4 = (e & 15) * 4;
        const int c = c0 + r;
        const int bg = b * G_ + (c >> 3);
        const float sc = g_rstd[bg] * w[c];
        const float sh = bvec[c] - g_mean[bg] * sc;
        float4 v = *reinterpret_cast<const float4*>(
            x + ((size_t)b * C_ + c) * L_ + l0 + l4);
        Ts[(l4 + 0) * 40 + r] = __float2half_rn(v.x * sc + sh);
        Ts[(l4 + 1) * 40 + r] = __float2half_rn(v.y * sc + sh);
        Ts[(l4 + 2) * 40 + r] = __float2half_rn(v.z * sc + sh);
        Ts[(l4 + 3) * 40 + r] = __float2half_rn(v.w * sc + sh);
    }
    __syncthreads();
    const int r = tid >> 2;
    const int q4 = (tid & 3) * 8;
    *reinterpret_cast<uint4*>(g_ht + ((size_t)b * L_ + l0 + r) * C_ + c0 + q4) =
        *reinterpret_cast<const uint4*>(Ts + r * 40 + q4);
}

// ---------------------------------------------------------------------------
// weight/bias conversion
// ---------------------------------------------------------------------------
__global__ void wconv_kernel(const float* __restrict__ qkvw,
                             const float* __restrict__ projw,
                             const float* __restrict__ qkvb) {
    const int row = blockIdx.x, t = threadIdx.x;
    if (row < 768) {
        const float s = (row < 256) ? QSCALE : 1.f;
        g_wh[row * 256 + t] = __float2half_rn(qkvw[row * 256 + t] * s);
        if (t == 0) g_bs[row] = qkvb[row] * s;
    } else {
        const int r = row - 768;
        g_wp[r * 256 + t] = __float2half_rn(projw[r * 256 + t]);
    }
}

// ---------------------------------------------------------------------------
// QKV GEMM (fp16 mma, 3-stage cp.async ring over 4 k-chunks).  [measured win]
// grid (L/128, 6, B), 256 threads. Epilogue routes Q,K -> (bh,l,d),
// V -> (bh,d,l).
// ---------------------------------------------------------------------------
__global__ void __launch_bounds__(256) qkv_mma_kernel() {
    extern __shared__ __align__(16) char smraw[];
    uint32_t* smu = reinterpret_cast<uint32_t*>(smraw);
    const uint32_t sb = smem_u32p(smraw);
    __half* Csh = reinterpret_cast<__half*>(smraw);
    uint32_t* Csu = reinterpret_cast<uint32_t*>(smraw);

    const int tid = threadIdx.x, wid = tid >> 5, lane = tid & 31;
    const int lg = lane >> 2, lt = lane & 3;
    const int nt = blockIdx.x, mt = blockIdx.y, b = blockIdx.z;
    const int m0 = mt * 128, n0g = nt * 128;
    const int moff = (wid & 3) * 32, noff = (wid >> 2) * 64;
    const __half* wsrc = g_wh;
    const __half* hsrc = g_ht + ((size_t)b * L_ + n0g) * 256;

    auto issueAB = [&](int kc, uint32_t ub /*u32 stage base*/) {
#pragma unroll
        for (int i = 0; i < 4; i++) {
            const int e = tid + i * 256;
            const int r = e >> 3, c8 = (e & 7) * 8;
            CP_ASYNC16(sb + ub * 4 + r * 144 + c8 * 2,
                       wsrc + (size_t)(m0 + r) * 256 + kc * 64 + c8);
            CP_ASYNC16(sb + (ub + 4608) * 4 + r * 144 + c8 * 2,
                       hsrc + (size_t)r * 256 + kc * 64 + c8);
        }
        CP_COMMIT();
    };

    issueAB(0, 0);
    issueAB(1, 9216);

    float oc[2][8][4] = {};
    uint32_t scb = 0, snb = 18432;
    for (int k = 0; k < 4; k++) {
        if (k < 3) asm volatile("cp.async.wait_group 1;" ::: "memory");
        else       asm volatile("cp.async.wait_group 0;" ::: "memory");
        __syncthreads();
        if (k + 2 < 4) issueAB(k + 2, snb);
        const uint32_t* Asu = smu + scb;
        const uint32_t* Bsu = smu + scb + 4608;
#pragma unroll
        for (int kc = 0; kc < 4; kc++) {
            uint32_t a[2][4];
#pragma unroll
            for (int m = 0; m < 2; m++) {
                const int r0 = moff + m * 16 + lg;
                a[m][0] = Asu[r0 * 36 + kc * 8 + lt];
                a[m][1] = Asu[(r0 + 8) * 36 + kc * 8 + lt];
                a[m][2] = Asu[r0 * 36 + kc * 8 + lt + 4];
                a[m][3] = Asu[(r0 + 8) * 36 + kc * 8 + lt + 4];
            }
#pragma unroll
            for (int n = 0; n < 8; n++) {
                const int brow = noff + n * 8 + lg;
                const uint32_t b0 = Bsu[brow * 36 + kc * 8 + lt];
                const uint32_t b1 = Bsu[brow * 36 + kc * 8 + lt + 4];
                mma_f16(oc[0][n], a[0], b0, b1);
                mma_f16(oc[1][n], a[1], b0, b1);
            }
        }
        scb = (scb == 18432) ? 0 : scb + 9216;
        snb = (snb == 18432) ? 0 : snb + 9216;
    }
    __syncthreads();

    const int sel = mt >> 1;
    const int h0 = (mt & 1) * 2;
    float bv[2][2];
#pragma unroll
    for (int m = 0; m < 2; m++) {
        bv[m][0] = g_bs[m0 + moff + m * 16 + lg];
        bv[m][1] = g_bs[m0 + moff + m * 16 + lg + 8];
    }

    if (sel < 2) {
        // transposed stage: Csh[l][m], stride 136
#pragma unroll
        for (int m = 0; m < 2; m++) {
            const int r = moff + m * 16 + lg;
#pragma unroll
            for (int n = 0; n < 8; n++) {
                const int col = noff + n * 8 + 2 * lt;
                Csh[col * 136 + r]           = __float2half_rn(oc[m][n][0] + bv[m][0]);
                Csh[(col + 1) * 136 + r]     = __float2half_rn(oc[m][n][1] + bv[m][0]);
                Csh[col * 136 + r + 8]       = __float2half_rn(oc[m][n][2] + bv[m][1]);
                Csh[(col + 1) * 136 + r + 8] = __float2half_rn(oc[m][n][3] + bv[m][1]);
            }
        }
        __syncthreads();
        __half* dst = (sel == 0 ? g_q : g_k);
#pragma unroll
        for (int i = 0; i < 8; i++) {
            const int e = tid + i * 256;
            const int l = e >> 4;
            const int seg = e & 15;
            const int hd = seg >> 3, q8 = (seg & 7) * 8;
            *reinterpret_cast<uint4*>(
                dst + ((size_t)(b * NH_ + h0 + hd) * L_ + n0g + l) * 64 + q8) =
                *reinterpret_cast<const uint4*>(Csh + l * 136 + hd * 64 + q8);
        }
    } else {
        // natural stage: Csh[m][n], stride 136 (68 u32)
#pragma unroll
        for (int m = 0; m < 2; m++) {
            const int r = moff + m * 16 + lg;
#pragma unroll
            for (int n = 0; n < 8; n++) {
                const int cu = (noff >> 1) + n * 4 + lt;
                Csu[r * 68 + cu]       = h2u(oc[m][n][0] + bv[m][0], oc[m][n][1] + bv[m][0]);
                Csu[(r + 8) * 68 + cu] = h2u(oc[m][n][2] + bv[m][1], oc[m][n][3] + bv[m][1]);
            }
        }
        __syncthreads();
#pragma unroll
        for (int i = 0; i < 8; i++) {
            const int e = tid + i * 256;
            const int r = e >> 4;
            const int c8 = (e & 15) * 8;
            const int hd = r >> 6, d = r & 63;
            *reinterpret_cast<uint4*>(
                g_v + ((size_t)((b * NH_ + h0 + hd) * 64 + d)) * L_ + n0g + c8) =
                *reinterpret_cast<const uint4*>(Csh + r * 136 + c8);
        }
    }
}

// ---------------------------------------------------------------------------
// Flash attention — exact R9 configuration (measured best).
// CTA = 128 thr = 4 warps, 128 queries (32/warp). 64-key tiles, double-
// buffered cp.async. log2-domain logits -> ex2.f16x2. Row sums via ones-row
// (V row 64 = 1.0).
// ---------------------------------------------------------------------------
__global__ void __launch_bounds__(128, 3) attn_kernel(__half* __restrict__ ot) {
    extern __shared__ __align__(16) __half smh[];
    uint32_t* smu = reinterpret_cast<uint32_t*>(smh);
    const uint32_t sb = smem_u32p(smh);

    const int tid = threadIdx.x, wid = tid >> 5, lane = tid & 31;
    const int lg = lane >> 2, lt = lane & 3;
    const int qb = wid * 32;
    const int l0 = blockIdx.x * 128;
    const int bh = blockIdx.y, b = bh >> 2, head = bh & 3;
    const __half* qg = g_q + ((size_t)bh * L_ + l0) * 64;
    const __half* kg = g_k + (size_t)bh * L_ * 64;
    const __half* vg = g_v + (size_t)bh * 64 * L_;

    // ones/zero const rows in both V buffers (rows 64..71)
    for (int e = tid; e < 576; e += 128) {
        const int buf = e / 288, rem = e % 288;
        const int row = 64 + rem / 36, c = rem % 36;
        smu[(((buf ? VOFF1 : VOFF0) + row * 72) >> 1) + c] =
            (row == 64) ? 0x3C003C00u : 0u;
    }
    // stage Q tile (128 x 64 halves) in K-buffer region, extract A-fragments
#pragma unroll
    for (int i = 0; i < 8; i++) {
        const int e = tid + i * 128;
        const int r = e >> 3, c8 = (e & 7) * 8;
        *reinterpret_cast<uint4*>(smh + r * 72 + c8) =
            *reinterpret_cast<const uint4*>(qg + (size_t)r * 64 + c8);
    }
    __syncthreads();
    uint32_t qa[2][4][4];
#pragma unroll
    for (int m = 0; m < 2; m++) {
        const int r0 = qb + m * 16 + lg;
#pragma unroll
        for (int kc = 0; kc < 4; kc++) {
            qa[m][kc][0] = smu[r0 * 36 + kc * 8 + lt];
            qa[m][kc][1] = smu[(r0 + 8) * 36 + kc * 8 + lt];
            qa[m][kc][2] = smu[r0 * 36 + kc * 8 + lt + 4];
            qa[m][kc][3] = smu[(r0 + 8) * 36 + kc * 8 + lt + 4];
        }
    }
    __syncthreads();   // Q reads complete before K0 is reused by cp.async

    auto issue = [&](int tile, uint32_t koff, uint32_t voff) {
        const __half* ks = kg + (size_t)tile * 64 * 64;
        const __half* vs = vg + tile * 64;
#pragma unroll
        for (int i = 0; i < 4; i++) {
            const int e = tid + i * 128;
            const int r = e >> 3, c8 = (e & 7) * 8;
            CP_ASYNC16(sb + (koff + r * 72 + c8) * 2, ks + (size_t)r * 64 + c8);
            CP_ASYNC16(sb + (voff + r * 72 + c8) * 2, vs + (size_t)r * L_ + c8);
        }
        CP_COMMIT();
    };

    float oc[2][9][4] = {};
    issue(0, KOFF0, VOFF0);

    for (int it = 0; it < 64; ++it) {
        const int cur = it & 1;
        const uint32_t koff = cur ? KOFF1 : KOFF0;
        const uint32_t voff = cur ? VOFF1 : VOFF0;
        if (it < 63) {
            issue(it + 1, cur ? KOFF0 : KOFF1, cur ? VOFF0 : VOFF1);
            asm volatile("cp.async.wait_group 1;" ::: "memory");
        } else {
            asm volatile("cp.async.wait_group 0;" ::: "memory");
        }
        __syncthreads();
        const uint32_t* Ku = smu + (koff >> 1);
        const uint32_t* Vu = smu + (voff >> 1);

#pragma unroll
        for (int kb = 0; kb < 4; kb++) {
            float ca0[4] = {}, cb0[4] = {}, ca1[4] = {}, cb1[4] = {};
            const int kr0 = kb * 16 + lg, kr1 = kr0 + 8;
#pragma unroll
            for (int kc = 0; kc < 4; kc++) {
                const uint32_t b0 = Ku[kr0 * 36 + kc * 8 + lt];
                const uint32_t b1 = Ku[kr0 * 36 + kc * 8 + lt + 4];
                mma_f16(ca0, qa[0][kc], b0, b1);
                mma_f16(cb0, qa[1][kc], b0, b1);
                const uint32_t d0 = Ku[kr1 * 36 + kc * 8 + lt];
                const uint32_t d1 = Ku[kr1 * 36 + kc * 8 + lt + 4];
                mma_f16(ca1, qa[0][kc], d0, d1);
                mma_f16(cb1, qa[1][kc], d0, d1);
            }
            // exp2 -> PV A-fragments (FA-2 register pipeline)
            uint32_t pa0[4] = {ex2h2(ca0[0], ca0[1]), ex2h2(ca0[2], ca0[3]),
                               ex2h2(ca1[0], ca1[1]), ex2h2(ca1[2], ca1[3])};
            uint32_t pa1[4] = {ex2h2(cb0[0], cb0[1]), ex2h2(cb0[2], cb0[3]),
                               ex2h2(cb1[0], cb1[1]), ex2h2(cb1[2], cb1[3])};
#pragma unroll
            for (int n = 0; n < 9; n++) {
                const int vrow = n * 8 + lg;
                const uint32_t b0 = Vu[vrow * 36 + kb * 8 + lt];
                const uint32_t b1 = Vu[vrow * 36 + kb * 8 + lt + 4];
                mma_f16(oc[0][n], pa0, b0, b1);
                mma_f16(oc[1][n], pa1, b0, b1);
            }
        }
        __syncthreads();
    }

    // row sums live in O column 64 (ones-row) at lt==0; broadcast across quad
    float inv[2][2];
#pragma unroll
    for (int m = 0; m < 2; m++) {
        const float r0 = __shfl_sync(0xffffffffu, oc[m][8][0], lane & ~3);
        const float r1 = __shfl_sync(0xffffffffu, oc[m][8][2], lane & ~3);
        inv[m][0] = 1.f / r0;
        inv[m][1] = 1.f / r1;
    }
    // stage O (l, d) fp16 in K-buffer region, write (b, l, c) rows
#pragma unroll
    for (int m = 0; m < 2; m++) {
        const int qrow = qb + m * 16 + lg;
#pragma unroll
        for (int n = 0; n < 8; n++) {
            smu[qrow * 36 + n * 4 + lt] =
                h2u(oc[m][n][0] * inv[m][0], oc[m][n][1] * inv[m][0]);
            smu[(qrow + 8) * 36 + n * 4 + lt] =
                h2u(oc[m][n][2] * inv[m][1], oc[m][n][3] * inv[m][1]);
        }
    }
    __syncthreads();
    __half* otp = ot + ((size_t)b * L_ + l0) * C_ + head * 64;
#pragma unroll
    for (int i = 0; i < 8; i++) {
        const int e = tid + i * 128;
        const int l = e >> 3, c8 = (e & 7) * 8;
        *reinterpret_cast<uint4*>(otp + (size_t)l * C_ + c8) =
            *reinterpret_cast<const uint4*>(smh + l * 72 + c8);
    }
}

// ---------------------------------------------------------------------------
// proj GEMM (fp16 mma) + bias + residual, fp32 output — exact R9 version
// grid (L/128, 2, B), 256 threads
// ---------------------------------------------------------------------------
__global__ void __launch_bounds__(256) proj_mma_kernel(
    const float* __restrict__ projb, const float* __restrict__ x,
    float* __restrict__ out)
{
    extern __shared__ __align__(16) char smraw[];
    __half* Ash = reinterpret_cast<__half*>(smraw);
    __half* Bsh = Ash + 128 * 72;
    uint32_t* Asu = reinterpret_cast<uint32_t*>(Ash);
    uint32_t* Bsu = reinterpret_cast<uint32_t*>(Bsh);

    const int tid = threadIdx.x, wid = tid >> 5, lane = tid & 31;
    const int lg = lane >> 2, lt = lane & 3;
    const int nt = blockIdx.x, mt = blockIdx.y, b = blockIdx.z;
    const int m0 = mt * 128, n0g = nt * 128;
    const int moff = (wid & 3) * 32, noff = (wid >> 2) * 64;

    float oc[2][8][4] = {};
    for (int k0 = 0; k0 < 256; k0 += 64) {
        __syncthreads();
#pragma unroll
        for (int i = 0; i < 4; i++) {
            const int e = tid + i * 256;
            const int r = e >> 3, c8 = (e & 7) * 8;
            *reinterpret_cast<uint4*>(Ash + r * 72 + c8) =
                *reinterpret_cast<const uint4*>(g_wp + (size_t)(m0 + r) * 256 + k0 + c8);
            *reinterpret_cast<uint4*>(Bsh + r * 72 + c8) =
                *reinterpret_cast<const uint4*>(g_ot + ((size_t)b * L_ + n0g + r) * 256 + k0 + c8);
        }
        __syncthreads();
#pragma unroll
        for (int kc = 0; kc < 4; kc++) {
            uint32_t a[2][4];
#pragma unroll
            for (int m = 0; m < 2; m++) {
                const int r0 = moff + m * 16 + lg;
                a[m][0] = Asu[r0 * 36 + kc * 8 + lt];
                a[m][1] = Asu[(r0 + 8) * 36 + kc * 8 + lt];
                a[m][2] = Asu[r0 * 36 + kc * 8 + lt + 4];
                a[m][3] = Asu[(r0 + 8) * 36 + kc * 8 + lt + 4];
            }
#pragma unroll
            for (int n = 0; n < 8; n++) {
                const int brow = noff + n * 8 + lg;
                const uint32_t b0 = Bsu[brow * 36 + kc * 8 + lt];
                const uint32_t b1 = Bsu[brow * 36 + kc * 8 + lt + 4];
                mma_f16(oc[0][n], a[0], b0, b1);
                mma_f16(oc[1][n], a[1], b0, b1);
            }
        }
    }
    // direct epilogue: bias + residual + fp32 store
#pragma unroll
    for (int m = 0; m < 2; m++) {
        const int crow = m0 + moff + m * 16 + lg;
        const float b0v = projb[crow], b1v = projb[crow + 8];
        const float* xp0 = x   + ((size_t)b * C_ + crow) * L_;
        float*       op0 = out + ((size_t)b * C_ + crow) * L_;
#pragma unroll
        for (int n = 0; n < 8; n++) {
            const int col = n0g + noff + n * 8 + 2 * lt;
            float2 xr = *reinterpret_cast<const float2*>(xp0 + col);
            *reinterpret_cast<float2*>(op0 + col) =
                make_float2(oc[m][n][0] + b0v + xr.x, oc[m][n][1] + b0v + xr.y);
            float2 xr2 = *reinterpret_cast<const float2*>(xp0 + 8 * L_ + col);
            *reinterpret_cast<float2*>(op0 + 8 * L_ + col) =
                make_float2(oc[m][n][2] + b1v + xr2.x, oc[m][n][3] + b1v + xr2.y);
        }
    }
}

// ---------------------------------------------------------------------------
// Host launcher
// ---------------------------------------------------------------------------
extern "C" void kernel_launch(void* const* d_in, const int* in_sizes, int n_in,
                              void* d_out, int out_size) {
    (void)in_sizes; (void)n_in; (void)out_size;
    const float* x      = (const float*)d_in[0];
    const float* gn_w   = (const float*)d_in[1];
    const float* gn_b   = (const float*)d_in[2];
    const float* qkv_w  = (const float*)d_in[3];
    const float* qkv_b  = (const float*)d_in[4];
    const float* proj_w = (const float*)d_in[5];
    const float* proj_b = (const float*)d_in[6];
    float* out = (float*)d_out;

    void* pot;
    cudaGetSymbolAddress(&pot, g_ot);
    __half* ot = (__half*)pot;

    // 1) GroupNorm -> fp16 transposed h
    gn_stats_kernel<<<B_ * G_, 256>>>(x);
    gn_apply_t_kernel<<<dim3(L_ / 64, C_ / 32, B_), 256>>>(x, gn_w, gn_b);

    // weight conversion
    wconv_kernel<<<1024, 256>>>(qkv_w, proj_w, qkv_b);

    // 2) QKV mma GEMM (3-stage ring) -> fp16 Q/K/V in attention layouts
    cudaFuncSetAttribute(qkv_mma_kernel,
                         cudaFuncAttributeMaxDynamicSharedMemorySize, GEMM_SMEM);
    qkv_mma_kernel<<<dim3(L_ / 128, 6, B_), 256, GEMM_SMEM>>>();

    // 3) Attention (R9 config: 128 q/CTA, grid 512)
    attn_kernel<<<dim3(L_ / 128, B_ * NH_), 128, ATTN_SMEM_H * 2>>>(ot);

    // 4) proj mma GEMM + bias + residual (R9 version)
    proj_mma_kernel<<<dim3(L_ / 128, 2, B_), 256, 2 * 128 * 72 * 2>>>(
        proj_b, x, out);
}

// round 15
// speedup vs baseline: 1.1388x; 1.0302x over previous
#include <cuda_runtime.h>
#include <cuda_fp16.h>
#include <cstdint>

// ---------------------------------------------------------------------------
// AttentionBlock, fully tensor-core (fp16 mma.m16n8k16, fp32 accum):
//   GroupNorm (fp16 transposed) -> QKV mma GEMM (3-stage cp.async ring)
//   -> FA-2 flash attention (R9 skeleton + ldmatrix B-fragments)
//   -> proj mma GEMM (3-stage cp.async ring) + residual.
// B=4, C=256, L=4096, 4 heads, d=64.
// ---------------------------------------------------------------------------

namespace {
constexpr int B_  = 4;
constexpr int C_  = 256;
constexpr int L_  = 4096;
constexpr int G_  = 32;
constexpr int NH_ = 4;
constexpr int CPG_ = C_ / G_;
constexpr float QSCALE = 0.125f * 1.4426950408889634f;   // d^-0.5 * log2(e)
// attention smem offsets (in halves): K 64x72 tiles, V 72x72 tiles
constexpr int KOFF0 = 0;
constexpr int KOFF1 = 4608;
constexpr int VOFF0 = 9216;
constexpr int VOFF1 = 14400;
constexpr int ATTN_SMEM_H = 19584;                       // halves -> 39168 B
// gemm smem: 3 stages x (A 128x72 + B 128x72) halves; stage = 9216 u32
constexpr int GEMM_SMEM = 3 * 9216 * 4;                  // 110592 B
}

// ---- fp16 mma (fp32 accumulate) ----
__device__ __forceinline__ void mma_f16(float c[4], const uint32_t a[4],
                                        uint32_t b0, uint32_t b1) {
    asm volatile(
        "mma.sync.aligned.m16n8k16.row.col.f32.f16.f16.f32 "
        "{%0,%1,%2,%3},{%4,%5,%6,%7},{%8,%9},{%0,%1,%2,%3};"
        : "+f"(c[0]), "+f"(c[1]), "+f"(c[2]), "+f"(c[3])
        : "r"(a[0]), "r"(a[1]), "r"(a[2]), "r"(a[3]), "r"(b0), "r"(b1));
}
__device__ __forceinline__ uint32_t h2u(float x, float y) {
    __half2 h = __floats2half2_rn(x, y);
    return *reinterpret_cast<uint32_t*>(&h);
}
__device__ __forceinline__ uint32_t ex2h2(float x, float y) {
    uint32_t h = h2u(x, y), r;
    asm("ex2.approx.f16x2 %0, %1;" : "=r"(r) : "r"(h));
    return r;
}
__device__ __forceinline__ uint32_t smem_u32p(const void* p) {
    uint32_t a;
    asm("{ .reg .u64 t; cvta.to.shared.u64 t, %1; cvt.u32.u64 %0, t; }" : "=r"(a) : "l"(p));
    return a;
}
#define CP_ASYNC16(dst, src) \
    asm volatile("cp.async.cg.shared.global [%0], [%1], 16;" :: "r"(dst), "l"(src))
#define CP_COMMIT() asm volatile("cp.async.commit_group;")
#define LDSM_X4(r0, r1, r2, r3, addr) \
    asm volatile("ldmatrix.sync.aligned.m8n8.x4.shared.b16 {%0,%1,%2,%3}, [%4];" \
                 : "=r"(r0), "=r"(r1), "=r"(r2), "=r"(r3) : "r"(addr))
#define LDSM_X2(r0, r1, addr) \
    asm volatile("ldmatrix.sync.aligned.m8n8.x2.shared.b16 {%0,%1}, [%2];" \
                 : "=r"(r0), "=r"(r1) : "r"(addr))

// ---- scratch (device globals) ----
__device__ __half g_ht[B_ * L_ * C_];        // GN output transposed (b, l, c)
__device__ __half g_q [B_ * NH_ * L_ * 64];  // (bh, l, d), prescaled by QSCALE
__device__ __half g_k [B_ * NH_ * L_ * 64];  // (bh, l, d)
__device__ __half g_v [B_ * NH_ * 64 * L_];  // (bh, d, l)
__device__ __half g_ot[B_ * L_ * C_];        // attention out transposed (b, l, c)
__device__ __half g_wh[768 * 256];           // qkv weights fp16 (Q rows prescaled)
__device__ __half g_wp[256 * 256];           // proj weights fp16
__device__ float  g_bs[768];                 // qkv bias (Q prescaled)
__device__ float  g_mean[B_ * G_];
__device__ float  g_rstd[B_ * G_];

// ---------------------------------------------------------------------------
// GroupNorm stats
// ---------------------------------------------------------------------------
__global__ void gn_stats_kernel(const float* __restrict__ x) {
    const int bg = blockIdx.x;
    const float4* p = reinterpret_cast<const float4*>(x) + (size_t)bg * (CPG_ * L_ / 4);
    float s = 0.f, ss = 0.f;
    for (int i = threadIdx.x; i < CPG_ * L_ / 4; i += blockDim.x) {
        float4 v = p[i];
        s  += v.x + v.y + v.z + v.w;
        ss += v.x * v.x + v.y * v.y + v.z * v.z + v.w * v.w;
    }
#pragma unroll
    for (int o = 16; o > 0; o >>= 1) {
        s  += __shfl_xor_sync(0xffffffffu, s, o);
        ss += __shfl_xor_sync(0xffffffffu, ss, o);
    }
    __shared__ float sh_s[8], sh_ss[8];
    const int w = threadIdx.x >> 5;
    if ((threadIdx.x & 31) == 0) { sh_s[w] = s; sh_ss[w] = ss; }
    __syncthreads();
    if (threadIdx.x == 0) {
        float S = 0.f, SS = 0.f;
#pragma unroll
        for (int i = 0; i < 8; i++) { S += sh_s[i]; SS += sh_ss[i]; }
        const float inv = 1.f / (float)(CPG_ * L_);
        const float mean = S * inv;
        const float var  = SS * inv - mean * mean;
        g_mean[bg] = mean;
        g_rstd[bg] = rsqrtf(var + 1e-5f);
    }
}

// ---------------------------------------------------------------------------
// GroupNorm apply, emitting fp16 h^T as (b, l, c)
// ---------------------------------------------------------------------------
__global__ void gn_apply_t_kernel(const float* __restrict__ x,
                                  const float* __restrict__ w,
                                  const float* __restrict__ bvec) {
    __shared__ __half Ts[64 * 40];
    const int b  = blockIdx.z;
    const int c0 = blockIdx.y * 32;
    const int l0 = blockIdx.x * 64;
    const int tid = threadIdx.x;
#pragma unroll
    for (int i = 0; i < 2; i++) {
        const int e = tid + i * 256;
        const int r = e >> 4;
        const int l4 = (e & 15) * 4;
        const int c = c0 + r;
        const int bg = b * G_ + (c >> 3);
        const float sc = g_rstd[bg] * w[c];
        const float sh = bvec[c] - g_mean[bg] * sc;
        float4 v = *reinterpret_cast<const float4*>(
            x + ((size_t)b * C_ + c) * L_ + l0 + l4);
        Ts[(l4 + 0) * 40 + r] = __float2half_rn(v.x * sc + sh);
        Ts[(l4 + 1) * 40 + r] = __float2half_rn(v.y * sc + sh);
        Ts[(l4 + 2) * 40 + r] = __float2half_rn(v.z * sc + sh);
        Ts[(l4 + 3) * 40 + r] = __float2half_rn(v.w * sc + sh);
    }
    __syncthreads();
    const int r = tid >> 2;
    const int q4 = (tid & 3) * 8;
    *reinterpret_cast<uint4*>(g_ht + ((size_t)b * L_ + l0 + r) * C_ + c0 + q4) =
        *reinterpret_cast<const uint4*>(Ts + r * 40 + q4);
}

// ---------------------------------------------------------------------------
// weight/bias conversion
// ---------------------------------------------------------------------------
__global__ void wconv_kernel(const float* __restrict__ qkvw,
                             const float* __restrict__ projw,
                             const float* __restrict__ qkvb) {
    const int row = blockIdx.x, t = threadIdx.x;
    if (row < 768) {
        const float s = (row < 256) ? QSCALE : 1.f;
        g_wh[row * 256 + t] = __float2half_rn(qkvw[row * 256 + t] * s);
        if (t == 0) g_bs[row] = qkvb[row] * s;
    } else {
        const int r = row - 768;
        g_wp[r * 256 + t] = __float2half_rn(projw[r * 256 + t]);
    }
}

// ---------------------------------------------------------------------------
// QKV GEMM (fp16 mma, 3-stage cp.async ring over 4 k-chunks).  [measured]
// grid (L/128, 6, B), 256 threads. Epilogue routes Q,K -> (bh,l,d),
// V -> (bh,d,l).
// ---------------------------------------------------------------------------
__global__ void __launch_bounds__(256) qkv_mma_kernel() {
    extern __shared__ __align__(16) char smraw[];
    uint32_t* smu = reinterpret_cast<uint32_t*>(smraw);
    const uint32_t sb = smem_u32p(smraw);
    __half* Csh = reinterpret_cast<__half*>(smraw);
    uint32_t* Csu = reinterpret_cast<uint32_t*>(smraw);

    const int tid = threadIdx.x, wid = tid >> 5, lane = tid & 31;
    const int lg = lane >> 2, lt = lane & 3;
    const int nt = blockIdx.x, mt = blockIdx.y, b = blockIdx.z;
    const int m0 = mt * 128, n0g = nt * 128;
    const int moff = (wid & 3) * 32, noff = (wid >> 2) * 64;
    const __half* wsrc = g_wh;
    const __half* hsrc = g_ht + ((size_t)b * L_ + n0g) * 256;

    auto issueAB = [&](int kc, uint32_t ub /*u32 stage base*/) {
#pragma unroll
        for (int i = 0; i < 4; i++) {
            const int e = tid + i * 256;
            const int r = e >> 3, c8 = (e & 7) * 8;
            CP_ASYNC16(sb + ub * 4 + r * 144 + c8 * 2,
                       wsrc + (size_t)(m0 + r) * 256 + kc * 64 + c8);
            CP_ASYNC16(sb + (ub + 4608) * 4 + r * 144 + c8 * 2,
                       hsrc + (size_t)r * 256 + kc * 64 + c8);
        }
        CP_COMMIT();
    };

    issueAB(0, 0);
    issueAB(1, 9216);

    float oc[2][8][4] = {};
    uint32_t scb = 0, snb = 18432;
    for (int k = 0; k < 4; k++) {
        if (k < 3) asm volatile("cp.async.wait_group 1;" ::: "memory");
        else       asm volatile("cp.async.wait_group 0;" ::: "memory");
        __syncthreads();
        if (k + 2 < 4) issueAB(k + 2, snb);
        const uint32_t* Asu = smu + scb;
        const uint32_t* Bsu = smu + scb + 4608;
#pragma unroll
        for (int kc = 0; kc < 4; kc++) {
            uint32_t a[2][4];
#pragma unroll
            for (int m = 0; m < 2; m++) {
                const int r0 = moff + m * 16 + lg;
                a[m][0] = Asu[r0 * 36 + kc * 8 + lt];
                a[m][1] = Asu[(r0 + 8) * 36 + kc * 8 + lt];
                a[m][2] = Asu[r0 * 36 + kc * 8 + lt + 4];
                a[m][3] = Asu[(r0 + 8) * 36 + kc * 8 + lt + 4];
            }
#pragma unroll
            for (int n = 0; n < 8; n++) {
                const int brow = noff + n * 8 + lg;
                const uint32_t b0 = Bsu[brow * 36 + kc * 8 + lt];
                const uint32_t b1 = Bsu[brow * 36 + kc * 8 + lt + 4];
                mma_f16(oc[0][n], a[0], b0, b1);
                mma_f16(oc[1][n], a[1], b0, b1);
            }
        }
        scb = (scb == 18432) ? 0 : scb + 9216;
        snb = (snb == 18432) ? 0 : snb + 9216;
    }
    __syncthreads();

    const int sel = mt >> 1;
    const int h0 = (mt & 1) * 2;
    float bv[2][2];
#pragma unroll
    for (int m = 0; m < 2; m++) {
        bv[m][0] = g_bs[m0 + moff + m * 16 + lg];
        bv[m][1] = g_bs[m0 + moff + m * 16 + lg + 8];
    }

    if (sel < 2) {
        // transposed stage: Csh[l][m], stride 136
#pragma unroll
        for (int m = 0; m < 2; m++) {
            const int r = moff + m * 16 + lg;
#pragma unroll
            for (int n = 0; n < 8; n++) {
                const int col = noff + n * 8 + 2 * lt;
                Csh[col * 136 + r]           = __float2half_rn(oc[m][n][0] + bv[m][0]);
                Csh[(col + 1) * 136 + r]     = __float2half_rn(oc[m][n][1] + bv[m][0]);
                Csh[col * 136 + r + 8]       = __float2half_rn(oc[m][n][2] + bv[m][1]);
                Csh[(col + 1) * 136 + r + 8] = __float2half_rn(oc[m][n][3] + bv[m][1]);
            }
        }
        __syncthreads();
        __half* dst = (sel == 0 ? g_q : g_k);
#pragma unroll
        for (int i = 0; i < 8; i++) {
            const int e = tid + i * 256;
            const int l = e >> 4;
            const int seg = e & 15;
            const int hd = seg >> 3, q8 = (seg & 7) * 8;
            *reinterpret_cast<uint4*>(
                dst + ((size_t)(b * NH_ + h0 + hd) * L_ + n0g + l) * 64 + q8) =
                *reinterpret_cast<const uint4*>(Csh + l * 136 + hd * 64 + q8);
        }
    } else {
        // natural stage: Csh[m][n], stride 136 (68 u32)
#pragma unroll
        for (int m = 0; m < 2; m++) {
            const int r = moff + m * 16 + lg;
#pragma unroll
            for (int n = 0; n < 8; n++) {
                const int cu = (noff >> 1) + n * 4 + lt;
                Csu[r * 68 + cu]       = h2u(oc[m][n][0] + bv[m][0], oc[m][n][1] + bv[m][0]);
                Csu[(r + 8) * 68 + cu] = h2u(oc[m][n][2] + bv[m][1], oc[m][n][3] + bv[m][1]);
            }
        }
        __syncthreads();
#pragma unroll
        for (int i = 0; i < 8; i++) {
            const int e = tid + i * 256;
            const int r = e >> 4;
            const int c8 = (e & 15) * 8;
            const int hd = r >> 6, d = r & 63;
            *reinterpret_cast<uint4*>(
                g_v + ((size_t)((b * NH_ + h0 + hd) * 64 + d)) * L_ + n0g + c8) =
                *reinterpret_cast<const uint4*>(Csh + r * 136 + c8);
        }
    }
}

// ---------------------------------------------------------------------------
// Flash attention — R9 skeleton, B-fragments via ldmatrix.
// CTA = 128 thr = 4 warps, 128 queries (32/warp). 64-key tiles, double-
// buffered cp.async. log2-domain logits -> ex2.f16x2. Row sums via ones-row
// (V row 64 = 1.0).
//
// LDSM lane mapping (x4): sel = lane>>3, r8 = lane&7:
//   matrix(sel) = rows [ (sel>>1)*8 + r8 ],  byte offset (sel&1)*16
//   -> r0 = b0(block0), r1 = b1(block0), r2 = b0(block1), r3 = b1(block1)
// Row pitch 144 B: the 8 rows of one matrix cover all 32 banks exactly once.
// ---------------------------------------------------------------------------
__global__ void __launch_bounds__(128, 3) attn_kernel(__half* __restrict__ ot) {
    extern __shared__ __align__(16) __half smh[];
    uint32_t* smu = reinterpret_cast<uint32_t*>(smh);
    const uint32_t sb = smem_u32p(smh);

    const int tid = threadIdx.x, wid = tid >> 5, lane = tid & 31;
    const int lg = lane >> 2, lt = lane & 3;
    const int qb = wid * 32;
    const int l0 = blockIdx.x * 128;
    const int bh = blockIdx.y, b = bh >> 2, head = bh & 3;
    const __half* qg = g_q + ((size_t)bh * L_ + l0) * 64;
    const __half* kg = g_k + (size_t)bh * L_ * 64;
    const __half* vg = g_v + (size_t)bh * 64 * L_;

    // ldmatrix per-lane byte offsets (within a tile buffer)
    const int r8 = lane & 7, lsel = lane >> 3;
    const uint32_t bfragOff = (uint32_t)(((lsel >> 1) * 8 + r8) * 144 + (lsel & 1) * 16);
    const uint32_t onesOff  = (uint32_t)((64 + (lane & 7)) * 144 + ((lane >> 3) & 1) * 16);

    // ones/zero const rows in both V buffers (rows 64..71)
    for (int e = tid; e < 576; e += 128) {
        const int buf = e / 288, rem = e % 288;
        const int row = 64 + rem / 36, c = rem % 36;
        smu[(((buf ? VOFF1 : VOFF0) + row * 72) >> 1) + c] =
            (row == 64) ? 0x3C003C00u : 0u;
    }
    // stage Q tile (128 x 64 halves) in K-buffer region, extract A-fragments
#pragma unroll
    for (int i = 0; i < 8; i++) {
        const int e = tid + i * 128;
        const int r = e >> 3, c8 = (e & 7) * 8;
        *reinterpret_cast<uint4*>(smh + r * 72 + c8) =
            *reinterpret_cast<const uint4*>(qg + (size_t)r * 64 + c8);
    }
    __syncthreads();
    uint32_t qa[2][4][4];
#pragma unroll
    for (int m = 0; m < 2; m++) {
        const int r0 = qb + m * 16 + lg;
#pragma unroll
        for (int kc = 0; kc < 4; kc++) {
            qa[m][kc][0] = smu[r0 * 36 + kc * 8 + lt];
            qa[m][kc][1] = smu[(r0 + 8) * 36 + kc * 8 + lt];
            qa[m][kc][2] = smu[r0 * 36 + kc * 8 + lt + 4];
            qa[m][kc][3] = smu[(r0 + 8) * 36 + kc * 8 + lt + 4];
        }
    }
    __syncthreads();   // Q reads complete before K0 is reused by cp.async

    auto issue = [&](int tile, uint32_t koff, uint32_t voff) {
        const __half* ks = kg + (size_t)tile * 64 * 64;
        const __half* vs = vg + tile * 64;
#pragma unroll
        for (int i = 0; i < 4; i++) {
            const int e = tid + i * 128;
            const int r = e >> 3, c8 = (e & 7) * 8;
            CP_ASYNC16(sb + (koff + r * 72 + c8) * 2, ks + (size_t)r * 64 + c8);
            CP_ASYNC16(sb + (voff + r * 72 + c8) * 2, vs + (size_t)r * L_ + c8);
        }
        CP_COMMIT();
    };

    float oc[2][9][4] = {};
    issue(0, KOFF0, VOFF0);

    for (int it = 0; it < 64; ++it) {
        const int cur = it & 1;
        const uint32_t koff = cur ? KOFF1 : KOFF0;
        const uint32_t voff = cur ? VOFF1 : VOFF0;
        if (it < 63) {
            issue(it + 1, cur ? KOFF0 : KOFF1, cur ? VOFF0 : VOFF1);
            asm volatile("cp.async.wait_group 1;" ::: "memory");
        } else {
            asm volatile("cp.async.wait_group 0;" ::: "memory");
        }
        __syncthreads();
        const uint32_t kbase = sb + koff * 2 + bfragOff;   // byte addr
        const uint32_t vbase = sb + voff * 2 + bfragOff;
        const uint32_t obase = sb + voff * 2 + onesOff;

#pragma unroll
        for (int kb = 0; kb < 4; kb++) {
            float ca0[4] = {}, cb0[4] = {}, ca1[4] = {}, cb1[4] = {};
            // S: per kc, one ldmatrix.x4 yields b0/b1 for both 8-key blocks
#pragma unroll
            for (int kc = 0; kc < 4; kc++) {
                uint32_t t0, t1, t2, t3;
                LDSM_X4(t0, t1, t2, t3, kbase + (uint32_t)(kb * 2304 + kc * 32));
                mma_f16(ca0, qa[0][kc], t0, t1);
                mma_f16(cb0, qa[1][kc], t0, t1);
                mma_f16(ca1, qa[0][kc], t2, t3);
                mma_f16(cb1, qa[1][kc], t2, t3);
            }
            // exp2 -> PV A-fragments (FA-2 register pipeline)
            uint32_t pa0[4] = {ex2h2(ca0[0], ca0[1]), ex2h2(ca0[2], ca0[3]),
                               ex2h2(ca1[0], ca1[1]), ex2h2(ca1[2], ca1[3])};
            uint32_t pa1[4] = {ex2h2(cb0[0], cb0[1]), ex2h2(cb0[2], cb0[3]),
                               ex2h2(cb1[0], cb1[1]), ex2h2(cb1[2], cb1[3])};
            // PV: per n-pair, one ldmatrix.x4; ones-row via ldmatrix.x2
#pragma unroll
            for (int p = 0; p < 4; p++) {
                uint32_t v0, v1, v2, v3;
                LDSM_X4(v0, v1, v2, v3, vbase + (uint32_t)(p * 2304 + kb * 32));
                mma_f16(oc[0][2 * p],     pa0, v0, v1);
                mma_f16(oc[1][2 * p],     pa1, v0, v1);
                mma_f16(oc[0][2 * p + 1], pa0, v2, v3);
                mma_f16(oc[1][2 * p + 1], pa1, v2, v3);
            }
            {
                uint32_t w0, w1;
                LDSM_X2(w0, w1, obase + (uint32_t)(kb * 32));
                mma_f16(oc[0][8], pa0, w0, w1);
                mma_f16(oc[1][8], pa1, w0, w1);
            }
        }
        __syncthreads();
    }

    // row sums live in O column 64 (ones-row) at lt==0; broadcast across quad
    float inv[2][2];
#pragma unroll
    for (int m = 0; m < 2; m++) {
        const float r0 = __shfl_sync(0xffffffffu, oc[m][8][0], lane & ~3);
        const float r1 = __shfl_sync(0xffffffffu, oc[m][8][2], lane & ~3);
        inv[m][0] = 1.f / r0;
        inv[m][1] = 1.f / r1;
    }
    // stage O (l, d) fp16 in K-buffer region, write (b, l, c) rows
#pragma unroll
    for (int m = 0; m < 2; m++) {
        const int qrow = qb + m * 16 + lg;
#pragma unroll
        for (int n = 0; n < 8; n++) {
            smu[qrow * 36 + n * 4 + lt] =
                h2u(oc[m][n][0] * inv[m][0], oc[m][n][1] * inv[m][0]);
            smu[(qrow + 8) * 36 + n * 4 + lt] =
                h2u(oc[m][n][2] * inv[m][1], oc[m][n][3] * inv[m][1]);
        }
    }
    __syncthreads();
    __half* otp = ot + ((size_t)b * L_ + l0) * C_ + head * 64;
#pragma unroll
    for (int i = 0; i < 8; i++) {
        const int e = tid + i * 128;
        const int l = e >> 3, c8 = (e & 7) * 8;
        *reinterpret_cast<uint4*>(otp + (size_t)l * C_ + c8) =
            *reinterpret_cast<const uint4*>(smh + l * 72 + c8);
    }
}

// ---------------------------------------------------------------------------
// proj GEMM (fp16 mma, 3-stage cp.async ring) + bias + residual, fp32 out
// grid (L/128, 2, B), 256 threads
// ---------------------------------------------------------------------------
__global__ void __launch_bounds__(256) proj_mma_kernel(
    const float* __restrict__ projb, const float* __restrict__ x,
    float* __restrict__ out)
{
    extern __shared__ __align__(16) char smraw[];
    uint32_t* smu = reinterpret_cast<uint32_t*>(smraw);
    const uint32_t sb = smem_u32p(smraw);

    const int tid = threadIdx.x, wid = tid >> 5, lane = tid & 31;
    const int lg = lane >> 2, lt = lane & 3;
    const int nt = blockIdx.x, mt = blockIdx.y, b = blockIdx.z;
    const int m0 = mt * 128, n0g = nt * 128;
    const int moff = (wid & 3) * 32, noff = (wid >> 2) * 64;
    const __half* wsrc = g_wp;
    const __half* osrc = g_ot + ((size_t)b * L_ + n0g) * 256;

    auto issueAB = [&](int kc, uint32_t ub) {
#pragma unroll
        for (int i = 0; i < 4; i++) {
            const int e = tid + i * 256;
            const int r = e >> 3, c8 = (e & 7) * 8;
            CP_ASYNC16(sb + ub * 4 + r * 144 + c8 * 2,
                       wsrc + (size_t)(m0 + r) * 256 + kc * 64 + c8);
            CP_ASYNC16(sb + (ub + 4608) * 4 + r * 144 + c8 * 2,
                       osrc + (size_t)r * 256 + kc * 64 + c8);
        }
        CP_COMMIT();
    };
    issueAB(0, 0);
    issueAB(1, 9216);

    float oc[2][8][4] = {};
    uint32_t scb = 0, snb = 18432;
    for (int k = 0; k < 4; k++) {
        if (k < 3) asm volatile("cp.async.wait_group 1;" ::: "memory");
        else       asm volatile("cp.async.wait_group 0;" ::: "memory");
        __syncthreads();
        if (k + 2 < 4) issueAB(k + 2, snb);
        const uint32_t* Asu = smu + scb;
        const uint32_t* Bsu = smu + scb + 4608;
#pragma unroll
        for (int kc = 0; kc < 4; kc++) {
            uint32_t a[2][4];
#pragma unroll
            for (int m = 0; m < 2; m++) {
                const int r0 = moff + m * 16 + lg;
                a[m][0] = Asu[r0 * 36 + kc * 8 + lt];
                a[m][1] = Asu[(r0 + 8) * 36 + kc * 8 + lt];
                a[m][2] = Asu[r0 * 36 + kc * 8 + lt + 4];
                a[m][3] = Asu[(r0 + 8) * 36 + kc * 8 + lt + 4];
            }
#pragma unroll
            for (int n = 0; n < 8; n++) {
                const int brow = noff + n * 8 + lg;
                const uint32_t b0 = Bsu[brow * 36 + kc * 8 + lt];
                const uint32_t b1 = Bsu[brow * 36 + kc * 8 + lt + 4];
                mma_f16(oc[0][n], a[0], b0, b1);
                mma_f16(oc[1][n], a[1], b0, b1);
            }
        }
        scb = (scb == 18432) ? 0 : scb + 9216;
        snb = (snb == 18432) ? 0 : snb + 9216;
    }
    // direct epilogue: bias + residual + fp32 store
#pragma unroll
    for (int m = 0; m < 2; m++) {
        const int crow = m0 + moff + m * 16 + lg;
        const float b0v = projb[crow], b1v = projb[crow + 8];
        const float* xp0 = x   + ((size_t)b * C_ + crow) * L_;
        float*       op0 = out + ((size_t)b * C_ + crow) * L_;
#pragma unroll
        for (int n = 0; n < 8; n++) {
            const int col = n0g + noff + n * 8 + 2 * lt;
            float2 xr = *reinterpret_cast<const float2*>(xp0 + col);
            *reinterpret_cast<float2*>(op0 + col) =
                make_float2(oc[m][n][0] + b0v + xr.x, oc[m][n][1] + b0v + xr.y);
            float2 xr2 = *reinterpret_cast<const float2*>(xp0 + 8 * L_ + col);
            *reinterpret_cast<float2*>(op0 + 8 * L_ + col) =
                make_float2(oc[m][n][2] + b1v + xr2.x, oc[m][n][3] + b1v + xr2.y);
        }
    }
}

// ---------------------------------------------------------------------------
// Host launcher
// ---------------------------------------------------------------------------
extern "C" void kernel_launch(void* const* d_in, const int* in_sizes, int n_in,
                              void* d_out, int out_size) {
    (void)in_sizes; (void)n_in; (void)out_size;
    const float* x      = (const float*)d_in[0];
    const float* gn_w   = (const float*)d_in[1];
    const float* gn_b   = (const float*)d_in[2];
    const float* qkv_w  = (const float*)d_in[3];
    const float* qkv_b  = (const float*)d_in[4];
    const float* proj_w = (const float*)d_in[5];
    const float* proj_b = (const float*)d_in[6];
    float* out = (float*)d_out;

    void* pot;
    cudaGetSymbolAddress(&pot, g_ot);
    __half* ot = (__half*)pot;

    // 1) GroupNorm -> fp16 transposed h
    gn_stats_kernel<<<B_ * G_, 256>>>(x);
    gn_apply_t_kernel<<<dim3(L_ / 64, C_ / 32, B_), 256>>>(x, gn_w, gn_b);

    // weight conversion
    wconv_kernel<<<1024, 256>>>(qkv_w, proj_w, qkv_b);

    // 2) QKV mma GEMM (3-stage ring) -> fp16 Q/K/V in attention layouts
    cudaFuncSetAttribute(qkv_mma_kernel,
                         cudaFuncAttributeMaxDynamicSharedMemorySize, GEMM_SMEM);
    qkv_mma_kernel<<<dim3(L_ / 128, 6, B_), 256, GEMM_SMEM>>>();

    // 3) Attention (R9 config + ldmatrix B-fragments)
    attn_kernel<<<dim3(L_ / 128, B_ * NH_), 128, ATTN_SMEM_H * 2>>>(ot);

    // 4) proj mma GEMM (3-stage ring) + bias + residual
    cudaFuncSetAttribute(proj_mma_kernel,
                         cudaFuncAttributeMaxDynamicSharedMemorySize, GEMM_SMEM);
    proj_mma_kernel<<<dim3(L_ / 128, 2, B_), 256, GEMM_SMEM>>>(proj_b, x, out);
}

// round 16
// speedup vs baseline: 1.1602x; 1.0188x over previous
#include <cuda_runtime.h>
#include <cuda_fp16.h>
#include <cstdint>

// ---------------------------------------------------------------------------
// AttentionBlock, fully tensor-core (fp16 mma.m16n8k16, fp32 accum):
//   GroupNorm (fp16 transposed) + fused weight conversion
//   -> QKV mma GEMM (3-stage cp.async ring, ldmatrix fragments)
//   -> FA-2 flash attention (R9 skeleton + ldmatrix B-fragments, frozen)
//   -> proj mma GEMM (3-stage ring, ldmatrix fragments) + residual.
// B=4, C=256, L=4096, 4 heads, d=64.
// ---------------------------------------------------------------------------

namespace {
constexpr int B_  = 4;
constexpr int C_  = 256;
constexpr int L_  = 4096;
constexpr int G_  = 32;
constexpr int NH_ = 4;
constexpr int CPG_ = C_ / G_;
constexpr float QSCALE = 0.125f * 1.4426950408889634f;   // d^-0.5 * log2(e)
// attention smem offsets (in halves): K 64x72 tiles, V 72x72 tiles
constexpr int KOFF0 = 0;
constexpr int KOFF1 = 4608;
constexpr int VOFF0 = 9216;
constexpr int VOFF1 = 14400;
constexpr int ATTN_SMEM_H = 19584;                       // halves -> 39168 B
// gemm smem: 3 stages x (A 128x72 + B 128x72) halves; stage = 9216 u32
constexpr int GEMM_SMEM = 3 * 9216 * 4;                  // 110592 B
}

// ---- fp16 mma (fp32 accumulate) ----
__device__ __forceinline__ void mma_f16(float c[4], const uint32_t a[4],
                                        uint32_t b0, uint32_t b1) {
    asm volatile(
        "mma.sync.aligned.m16n8k16.row.col.f32.f16.f16.f32 "
        "{%0,%1,%2,%3},{%4,%5,%6,%7},{%8,%9},{%0,%1,%2,%3};"
        : "+f"(c[0]), "+f"(c[1]), "+f"(c[2]), "+f"(c[3])
        : "r"(a[0]), "r"(a[1]), "r"(a[2]), "r"(a[3]), "r"(b0), "r"(b1));
}
__device__ __forceinline__ uint32_t h2u(float x, float y) {
    __half2 h = __floats2half2_rn(x, y);
    return *reinterpret_cast<uint32_t*>(&h);
}
__device__ __forceinline__ uint32_t ex2h2(float x, float y) {
    uint32_t h = h2u(x, y), r;
    asm("ex2.approx.f16x2 %0, %1;" : "=r"(r) : "r"(h));
    return r;
}
__device__ __forceinline__ uint32_t smem_u32p(const void* p) {
    uint32_t a;
    asm("{ .reg .u64 t; cvta.to.shared.u64 t, %1; cvt.u32.u64 %0, t; }" : "=r"(a) : "l"(p));
    return a;
}
#define CP_ASYNC16(dst, src) \
    asm volatile("cp.async.cg.shared.global [%0], [%1], 16;" :: "r"(dst), "l"(src))
#define CP_COMMIT() asm volatile("cp.async.commit_group;")
#define LDSM_X4(r0, r1, r2, r3, addr) \
    asm volatile("ldmatrix.sync.aligned.m8n8.x4.shared.b16 {%0,%1,%2,%3}, [%4];" \
                 : "=r"(r0), "=r"(r1), "=r"(r2), "=r"(r3) : "r"(addr))
#define LDSM_X2(r0, r1, addr) \
    asm volatile("ldmatrix.sync.aligned.m8n8.x2.shared.b16 {%0,%1}, [%2];" \
                 : "=r"(r0), "=r"(r1) : "r"(addr))

// ---- scratch (device globals) ----
__device__ __half g_ht[B_ * L_ * C_];        // GN output transposed (b, l, c)
__device__ __half g_q [B_ * NH_ * L_ * 64];  // (bh, l, d), prescaled by QSCALE
__device__ __half g_k [B_ * NH_ * L_ * 64];  // (bh, l, d)
__device__ __half g_v [B_ * NH_ * 64 * L_];  // (bh, d, l)
__device__ __half g_ot[B_ * L_ * C_];        // attention out transposed (b, l, c)
__device__ __half g_wh[768 * 256];           // qkv weights fp16 (Q rows prescaled)
__device__ __half g_wp[256 * 256];           // proj weights fp16
__device__ float  g_bs[768];                 // qkv bias (Q prescaled)
__device__ float  g_mean[B_ * G_];
__device__ float  g_rstd[B_ * G_];

// ---------------------------------------------------------------------------
// Fused GroupNorm stats + weight/bias conversion.
// blocks 0..127: stats for (batch, group). blocks 128..1151: wconv rows.
// ---------------------------------------------------------------------------
__global__ void gn_stats_wconv_kernel(const float* __restrict__ x,
                                      const float* __restrict__ qkvw,
                                      const float* __restrict__ projw,
                                      const float* __restrict__ qkvb) {
    if (blockIdx.x >= 128) {
        const int row = blockIdx.x - 128, t = threadIdx.x;
        if (row < 768) {
            const float s = (row < 256) ? QSCALE : 1.f;
            g_wh[row * 256 + t] = __float2half_rn(qkvw[row * 256 + t] * s);
            if (t == 0) g_bs[row] = qkvb[row] * s;
        } else {
            const int r = row - 768;
            g_wp[r * 256 + t] = __float2half_rn(projw[r * 256 + t]);
        }
        return;
    }
    const int bg = blockIdx.x;
    const float4* p = reinterpret_cast<const float4*>(x) + (size_t)bg * (CPG_ * L_ / 4);
    float s = 0.f, ss = 0.f;
    for (int i = threadIdx.x; i < CPG_ * L_ / 4; i += blockDim.x) {
        float4 v = p[i];
        s  += v.x + v.y + v.z + v.w;
        ss += v.x * v.x + v.y * v.y + v.z * v.z + v.w * v.w;
    }
#pragma unroll
    for (int o = 16; o > 0; o >>= 1) {
        s  += __shfl_xor_sync(0xffffffffu, s, o);
        ss += __shfl_xor_sync(0xffffffffu, ss, o);
    }
    __shared__ float sh_s[8], sh_ss[8];
    const int w = threadIdx.x >> 5;
    if ((threadIdx.x & 31) == 0) { sh_s[w] = s; sh_ss[w] = ss; }
    __syncthreads();
    if (threadIdx.x == 0) {
        float S = 0.f, SS = 0.f;
#pragma unroll
        for (int i = 0; i < 8; i++) { S += sh_s[i]; SS += sh_ss[i]; }
        const float inv = 1.f / (float)(CPG_ * L_);
        const float mean = S * inv;
        const float var  = SS * inv - mean * mean;
        g_mean[bg] = mean;
        g_rstd[bg] = rsqrtf(var + 1e-5f);
    }
}

// ---------------------------------------------------------------------------
// GroupNorm apply, emitting fp16 h^T as (b, l, c)
// ---------------------------------------------------------------------------
__global__ void gn_apply_t_kernel(const float* __restrict__ x,
                                  const float* __restrict__ w,
                                  const float* __restrict__ bvec) {
    __shared__ __half Ts[64 * 40];
    const int b  = blockIdx.z;
    const int c0 = blockIdx.y * 32;
    const int l0 = blockIdx.x * 64;
    const int tid = threadIdx.x;
#pragma unroll
    for (int i = 0; i < 2; i++) {
        const int e = tid + i * 256;
        const int r = e >> 4;
        const int l4 = (e & 15) * 4;
        const int c = c0 + r;
        const int bg = b * G_ + (c >> 3);
        const float sc = g_rstd[bg] * w[c];
        const float sh = bvec[c] - g_mean[bg] * sc;
        float4 v = *reinterpret_cast<const float4*>(
            x + ((size_t)b * C_ + c) * L_ + l0 + l4);
        Ts[(l4 + 0) * 40 + r] = __float2half_rn(v.x * sc + sh);
        Ts[(l4 + 1) * 40 + r] = __float2half_rn(v.y * sc + sh);
        Ts[(l4 + 2) * 40 + r] = __float2half_rn(v.z * sc + sh);
        Ts[(l4 + 3) * 40 + r] = __float2half_rn(v.w * sc + sh);
    }
    __syncthreads();
    const int r = tid >> 2;
    const int q4 = (tid & 3) * 8;
    *reinterpret_cast<uint4*>(g_ht + ((size_t)b * L_ + l0 + r) * C_ + c0 + q4) =
        *reinterpret_cast<const uint4*>(Ts + r * 40 + q4);
}

// ---------------------------------------------------------------------------
// QKV GEMM (fp16 mma, 3-stage cp.async ring, ldmatrix fragments).
// grid (L/128, 6, B), 256 threads. Epilogue routes Q,K -> (bh,l,d),
// V -> (bh,d,l).
// ---------------------------------------------------------------------------
__global__ void __launch_bounds__(256) qkv_mma_kernel() {
    extern __shared__ __align__(16) char smraw[];
    const uint32_t sb = smem_u32p(smraw);
    __half* Csh = reinterpret_cast<__half*>(smraw);
    uint32_t* Csu = reinterpret_cast<uint32_t*>(smraw);

    const int tid = threadIdx.x, wid = tid >> 5, lane = tid & 31;
    const int lg = lane >> 2, lt = lane & 3;
    const int nt = blockIdx.x, mt = blockIdx.y, b = blockIdx.z;
    const int m0 = mt * 128, n0g = nt * 128;
    const int moff = (wid & 3) * 32, noff = (wid >> 2) * 64;
    const __half* wsrc = g_wh;
    const __half* hsrc = g_ht + ((size_t)b * L_ + n0g) * 256;

    // ldmatrix lane offsets (bytes, within a 144B-pitch tile)
    const int r8 = lane & 7;
    const uint32_t aOff = (uint32_t)((moff + ((lane >> 3) & 1) * 8 + r8) * 144 +
                                     ((lane >> 4) & 1) * 16);      // A: row-blk by bit3
    const uint32_t bOff = (uint32_t)((noff + ((lane >> 4) & 1) * 8 + r8) * 144 +
                                     ((lane >> 3) & 1) * 16);      // B: row-blk by bit4

    auto issueAB = [&](int kc, uint32_t ub /*u32 stage base*/) {
#pragma unroll
        for (int i = 0; i < 4; i++) {
            const int e = tid + i * 256;
            const int r = e >> 3, c8 = (e & 7) * 8;
            CP_ASYNC16(sb + ub * 4 + r * 144 + c8 * 2,
                       wsrc + (size_t)(m0 + r) * 256 + kc * 64 + c8);
            CP_ASYNC16(sb + (ub + 4608) * 4 + r * 144 + c8 * 2,
                       hsrc + (size_t)r * 256 + kc * 64 + c8);
        }
        CP_COMMIT();
    };

    issueAB(0, 0);
    issueAB(1, 9216);

    float oc[2][8][4] = {};
    uint32_t scb = 0, snb = 18432;
    for (int k = 0; k < 4; k++) {
        if (k < 3) asm volatile("cp.async.wait_group 1;" ::: "memory");
        else       asm volatile("cp.async.wait_group 0;" ::: "memory");
        __syncthreads();
        if (k + 2 < 4) issueAB(k + 2, snb);
        const uint32_t abase = sb + scb * 4 + aOff;
        const uint32_t bbase = sb + (scb + 4608) * 4 + bOff;
#pragma unroll
        for (int kc = 0; kc < 4; kc++) {
            uint32_t a[2][4];
            LDSM_X4(a[0][0], a[0][1], a[0][2], a[0][3], abase + (uint32_t)(kc * 32));
            LDSM_X4(a[1][0], a[1][1], a[1][2], a[1][3], abase + (uint32_t)(2304 + kc * 32));
#pragma unroll
            for (int p = 0; p < 4; p++) {
                uint32_t v0, v1, v2, v3;
                LDSM_X4(v0, v1, v2, v3, bbase + (uint32_t)(p * 2304 + kc * 32));
                mma_f16(oc[0][2 * p],     a[0], v0, v1);
                mma_f16(oc[1][2 * p],     a[1], v0, v1);
                mma_f16(oc[0][2 * p + 1], a[0], v2, v3);
                mma_f16(oc[1][2 * p + 1], a[1], v2, v3);
            }
        }
        scb = (scb == 18432) ? 0 : scb + 9216;
        snb = (snb == 18432) ? 0 : snb + 9216;
    }
    __syncthreads();

    const int sel = mt >> 1;
    const int h0 = (mt & 1) * 2;
    float bv[2][2];
#pragma unroll
    for (int m = 0; m < 2; m++) {
        bv[m][0] = g_bs[m0 + moff + m * 16 + lg];
        bv[m][1] = g_bs[m0 + moff + m * 16 + lg + 8];
    }

    if (sel < 2) {
        // transposed stage: Csh[l][m], stride 136
#pragma unroll
        for (int m = 0; m < 2; m++) {
            const int r = moff + m * 16 + lg;
#pragma unroll
            for (int n = 0; n < 8; n++) {
                const int col = noff + n * 8 + 2 * lt;
                Csh[col * 136 + r]           = __float2half_rn(oc[m][n][0] + bv[m][0]);
                Csh[(col + 1) * 136 + r]     = __float2half_rn(oc[m][n][1] + bv[m][0]);
                Csh[col * 136 + r + 8]       = __float2half_rn(oc[m][n][2] + bv[m][1]);
                Csh[(col + 1) * 136 + r + 8] = __float2half_rn(oc[m][n][3] + bv[m][1]);
            }
        }
        __syncthreads();
        __half* dst = (sel == 0 ? g_q : g_k);
#pragma unroll
        for (int i = 0; i < 8; i++) {
            const int e = tid + i * 256;
            const int l = e >> 4;
            const int seg = e & 15;
            const int hd = seg >> 3, q8 = (seg & 7) * 8;
            *reinterpret_cast<uint4*>(
                dst + ((size_t)(b * NH_ + h0 + hd) * L_ + n0g + l) * 64 + q8) =
                *reinterpret_cast<const uint4*>(Csh + l * 136 + hd * 64 + q8);
        }
    } else {
        // natural stage: Csh[m][n], stride 136 (68 u32)
#pragma unroll
        for (int m = 0; m < 2; m++) {
            const int r = moff + m * 16 + lg;
#pragma unroll
            for (int n = 0; n < 8; n++) {
                const int cu = (noff >> 1) + n * 4 + lt;
                Csu[r * 68 + cu]       = h2u(oc[m][n][0] + bv[m][0], oc[m][n][1] + bv[m][0]);
                Csu[(r + 8) * 68 + cu] = h2u(oc[m][n][2] + bv[m][1], oc[m][n][3] + bv[m][1]);
            }
        }
        __syncthreads();
#pragma unroll
        for (int i = 0; i < 8; i++) {
            const int e = tid + i * 256;
            const int r = e >> 4;
            const int c8 = (e & 15) * 8;
            const int hd = r >> 6, d = r & 63;
            *reinterpret_cast<uint4*>(
                g_v + ((size_t)((b * NH_ + h0 + hd) * 64 + d)) * L_ + n0g + c8) =
                *reinterpret_cast<const uint4*>(Csh + r * 136 + c8);
        }
    }
}

// ---------------------------------------------------------------------------
// Flash attention — R9 skeleton + ldmatrix B-fragments (frozen, measured).
// CTA = 128 thr = 4 warps, 128 queries (32/warp). 64-key tiles, double-
// buffered cp.async. log2-domain logits -> ex2.f16x2. Row sums via ones-row.
// ---------------------------------------------------------------------------
__global__ void __launch_bounds__(128, 3) attn_kernel(__half* __restrict__ ot) {
    extern __shared__ __align__(16) __half smh[];
    uint32_t* smu = reinterpret_cast<uint32_t*>(smh);
    const uint32_t sb = smem_u32p(smh);

    const int tid = threadIdx.x, wid = tid >> 5, lane = tid & 31;
    const int lg = lane >> 2, lt = lane & 3;
    const int qb = wid * 32;
    const int l0 = blockIdx.x * 128;
    const int bh = blockIdx.y, b = bh >> 2, head = bh & 3;
    const __half* qg = g_q + ((size_t)bh * L_ + l0) * 64;
    const __half* kg = g_k + (size_t)bh * L_ * 64;
    const __half* vg = g_v + (size_t)bh * 64 * L_;

    const int r8 = lane & 7, lsel = lane >> 3;
    const uint32_t bfragOff = (uint32_t)(((lsel >> 1) * 8 + r8) * 144 + (lsel & 1) * 16);
    const uint32_t onesOff  = (uint32_t)((64 + (lane & 7)) * 144 + ((lane >> 3) & 1) * 16);

    for (int e = tid; e < 576; e += 128) {
        const int buf = e / 288, rem = e % 288;
        const int row = 64 + rem / 36, c = rem % 36;
        smu[(((buf ? VOFF1 : VOFF0) + row * 72) >> 1) + c] =
            (row == 64) ? 0x3C003C00u : 0u;
    }
#pragma unroll
    for (int i = 0; i < 8; i++) {
        const int e = tid + i * 128;
        const int r = e >> 3, c8 = (e & 7) * 8;
        *reinterpret_cast<uint4*>(smh + r * 72 + c8) =
            *reinterpret_cast<const uint4*>(qg + (size_t)r * 64 + c8);
    }
    __syncthreads();
    uint32_t qa[2][4][4];
#pragma unroll
    for (int m = 0; m < 2; m++) {
        const int r0 = qb + m * 16 + lg;
#pragma unroll
        for (int kc = 0; kc < 4; kc++) {
            qa[m][kc][0] = smu[r0 * 36 + kc * 8 + lt];
            qa[m][kc][1] = smu[(r0 + 8) * 36 + kc * 8 + lt];
            qa[m][kc][2] = smu[r0 * 36 + kc * 8 + lt + 4];
            qa[m][kc][3] = smu[(r0 + 8) * 36 + kc * 8 + lt + 4];
        }
    }
    __syncthreads();

    auto issue = [&](int tile, uint32_t koff, uint32_t voff) {
        const __half* ks = kg + (size_t)tile * 64 * 64;
        const __half* vs = vg + tile * 64;
#pragma unroll
        for (int i = 0; i < 4; i++) {
            const int e = tid + i * 128;
            const int r = e >> 3, c8 = (e & 7) * 8;
            CP_ASYNC16(sb + (koff + r * 72 + c8) * 2, ks + (size_t)r * 64 + c8);
            CP_ASYNC16(sb + (voff + r * 72 + c8) * 2, vs + (size_t)r * L_ + c8);
        }
        CP_COMMIT();
    };

    float oc[2][9][4] = {};
    issue(0, KOFF0, VOFF0);

    for (int it = 0; it < 64; ++it) {
        const int cur = it & 1;
        const uint32_t koff = cur ? KOFF1 : KOFF0;
        const uint32_t voff = cur ? VOFF1 : VOFF0;
        if (it < 63) {
            issue(it + 1, cur ? KOFF0 : KOFF1, cur ? VOFF0 : VOFF1);
            asm volatile("cp.async.wait_group 1;" ::: "memory");
        } else {
            asm volatile("cp.async.wait_group 0;" ::: "memory");
        }
        __syncthreads();
        const uint32_t kbase = sb + koff * 2 + bfragOff;
        const uint32_t vbase = sb + voff * 2 + bfragOff;
        const uint32_t obase = sb + voff * 2 + onesOff;

#pragma unroll
        for (int kb = 0; kb < 4; kb++) {
            float ca0[4] = {}, cb0[4] = {}, ca1[4] = {}, cb1[4] = {};
#pragma unroll
            for (int kc = 0; kc < 4; kc++) {
                uint32_t t0, t1, t2, t3;
                LDSM_X4(t0, t1, t2, t3, kbase + (uint32_t)(kb * 2304 + kc * 32));
                mma_f16(ca0, qa[0][kc], t0, t1);
                mma_f16(cb0, qa[1][kc], t0, t1);
                mma_f16(ca1, qa[0][kc], t2, t3);
                mma_f16(cb1, qa[1][kc], t2, t3);
            }
            uint32_t pa0[4] = {ex2h2(ca0[0], ca0[1]), ex2h2(ca0[2], ca0[3]),
                               ex2h2(ca1[0], ca1[1]), ex2h2(ca1[2], ca1[3])};
            uint32_t pa1[4] = {ex2h2(cb0[0], cb0[1]), ex2h2(cb0[2], cb0[3]),
                               ex2h2(cb1[0], cb1[1]), ex2h2(cb1[2], cb1[3])};
#pragma unroll
            for (int p = 0; p < 4; p++) {
                uint32_t v0, v1, v2, v3;
                LDSM_X4(v0, v1, v2, v3, vbase + (uint32_t)(p * 2304 + kb * 32));
                mma_f16(oc[0][2 * p],     pa0, v0, v1);
                mma_f16(oc[1][2 * p],     pa1, v0, v1);
                mma_f16(oc[0][2 * p + 1], pa0, v2, v3);
                mma_f16(oc[1][2 * p + 1], pa1, v2, v3);
            }
            {
                uint32_t w0, w1;
                LDSM_X2(w0, w1, obase + (uint32_t)(kb * 32));
                mma_f16(oc[0][8], pa0, w0, w1);
                mma_f16(oc[1][8], pa1, w0, w1);
            }
        }
        __syncthreads();
    }

    float inv[2][2];
#pragma unroll
    for (int m = 0; m < 2; m++) {
        const float r0 = __shfl_sync(0xffffffffu, oc[m][8][0], lane & ~3);
        const float r1 = __shfl_sync(0xffffffffu, oc[m][8][2], lane & ~3);
        inv[m][0] = 1.f / r0;
        inv[m][1] = 1.f / r1;
    }
#pragma unroll
    for (int m = 0; m < 2; m++) {
        const int qrow = qb + m * 16 + lg;
#pragma unroll
        for (int n = 0; n < 8; n++) {
            smu[qrow * 36 + n * 4 + lt] =
                h2u(oc[m][n][0] * inv[m][0], oc[m][n][1] * inv[m][0]);
            smu[(qrow + 8) * 36 + n * 4 + lt] =
                h2u(oc[m][n][2] * inv[m][1], oc[m][n][3] * inv[m][1]);
        }
    }
    __syncthreads();
    __half* otp = ot + ((size_t)b * L_ + l0) * C_ + head * 64;
#pragma unroll
    for (int i = 0; i < 8; i++) {
        const int e = tid + i * 128;
        const int l = e >> 3, c8 = (e & 7) * 8;
        *reinterpret_cast<uint4*>(otp + (size_t)l * C_ + c8) =
            *reinterpret_cast<const uint4*>(smh + l * 72 + c8);
    }
}

// ---------------------------------------------------------------------------
// proj GEMM (fp16 mma, 3-stage ring, ldmatrix fragments) + bias + residual
// grid (L/128, 2, B), 256 threads
// ---------------------------------------------------------------------------
__global__ void __launch_bounds__(256) proj_mma_kernel(
    const float* __restrict__ projb, const float* __restrict__ x,
    float* __restrict__ out)
{
    extern __shared__ __align__(16) char smraw[];
    const uint32_t sb = smem_u32p(smraw);

    const int tid = threadIdx.x, wid = tid >> 5, lane = tid & 31;
    const int lg = lane >> 2, lt = lane & 3;
    const int nt = blockIdx.x, mt = blockIdx.y, b = blockIdx.z;
    const int m0 = mt * 128, n0g = nt * 128;
    const int moff = (wid & 3) * 32, noff = (wid >> 2) * 64;
    const __half* wsrc = g_wp;
    const __half* osrc = g_ot + ((size_t)b * L_ + n0g) * 256;

    const int r8 = lane & 7;
    const uint32_t aOff = (uint32_t)((moff + ((lane >> 3) & 1) * 8 + r8) * 144 +
                                     ((lane >> 4) & 1) * 16);
    const uint32_t bOff = (uint32_t)((noff + ((lane >> 4) & 1) * 8 + r8) * 144 +
                                     ((lane >> 3) & 1) * 16);

    auto issueAB = [&](int kc, uint32_t ub) {
#pragma unroll
        for (int i = 0; i < 4; i++) {
            const int e = tid + i * 256;
            const int r = e >> 3, c8 = (e & 7) * 8;
            CP_ASYNC16(sb + ub * 4 + r * 144 + c8 * 2,
                       wsrc + (size_t)(m0 + r) * 256 + kc * 64 + c8);
            CP_ASYNC16(sb + (ub + 4608) * 4 + r * 144 + c8 * 2,
                       osrc + (size_t)r * 256 + kc * 64 + c8);
        }
        CP_COMMIT();
    };
    issueAB(0, 0);
    issueAB(1, 9216);

    float oc[2][8][4] = {};
    uint32_t scb = 0, snb = 18432;
    for (int k = 0; k < 4; k++) {
        if (k < 3) asm volatile("cp.async.wait_group 1;" ::: "memory");
        else       asm volatile("cp.async.wait_group 0;" ::: "memory");
        __syncthreads();
        if (k + 2 < 4) issueAB(k + 2, snb);
        const uint32_t abase = sb + scb * 4 + aOff;
        const uint32_t bbase = sb + (scb + 4608) * 4 + bOff;
#pragma unroll
        for (int kc = 0; kc < 4; kc++) {
            uint32_t a[2][4];
            LDSM_X4(a[0][0], a[0][1], a[0][2], a[0][3], abase + (uint32_t)(kc * 32));
            LDSM_X4(a[1][0], a[1][1], a[1][2], a[1][3], abase + (uint32_t)(2304 + kc * 32));
#pragma unroll
            for (int p = 0; p < 4; p++) {
                uint32_t v0, v1, v2, v3;
                LDSM_X4(v0, v1, v2, v3, bbase + (uint32_t)(p * 2304 + kc * 32));
                mma_f16(oc[0][2 * p],     a[0], v0, v1);
                mma_f16(oc[1][2 * p],     a[1], v0, v1);
                mma_f16(oc[0][2 * p + 1], a[0], v2, v3);
                mma_f16(oc[1][2 * p + 1], a[1], v2, v3);
            }
        }
        scb = (scb == 18432) ? 0 : scb + 9216;
        snb = (snb == 18432) ? 0 : snb + 9216;
    }
    // direct epilogue: bias + residual + fp32 store
#pragma unroll
    for (int m = 0; m < 2; m++) {
        const int crow = m0 + moff + m * 16 + lg;
        const float b0v = projb[crow], b1v = projb[crow + 8];
        const float* xp0 = x   + ((size_t)b * C_ + crow) * L_;
        float*       op0 = out + ((size_t)b * C_ + crow) * L_;
#pragma unroll
        for (int n = 0; n < 8; n++) {
            const int col = n0g + noff + n * 8 + 2 * lt;
            float2 xr = *reinterpret_cast<const float2*>(xp0 + col);
            *reinterpret_cast<float2*>(op0 + col) =
                make_float2(oc[m][n][0] + b0v + xr.x, oc[m][n][1] + b0v + xr.y);
            float2 xr2 = *reinterpret_cast<const float2*>(xp0 + 8 * L_ + col);
            *reinterpret_cast<float2*>(op0 + 8 * L_ + col) =
                make_float2(oc[m][n][2] + b1v + xr2.x, oc[m][n][3] + b1v + xr2.y);
        }
    }
}

// ---------------------------------------------------------------------------
// Host launcher
// ---------------------------------------------------------------------------
extern "C" void kernel_launch(void* const* d_in, const int* in_sizes, int n_in,
                              void* d_out, int out_size) {
    (void)in_sizes; (void)n_in; (void)out_size;
    const float* x      = (const float*)d_in[0];
    const float* gn_w   = (const float*)d_in[1];
    const float* gn_b   = (const float*)d_in[2];
    const float* qkv_w  = (const float*)d_in[3];
    const float* qkv_b  = (const float*)d_in[4];
    const float* proj_w = (const float*)d_in[5];
    const float* proj_b = (const float*)d_in[6];
    float* out = (float*)d_out;

    void* pot;
    cudaGetSymbolAddress(&pot, g_ot);
    __half* ot = (__half*)pot;

    // 1) Fused GroupNorm stats + weight conversion, then GN apply
    gn_stats_wconv_kernel<<<1152, 256>>>(x, qkv_w, proj_w, qkv_b);
    gn_apply_t_kernel<<<dim3(L_ / 64, C_ / 32, B_), 256>>>(x, gn_w, gn_b);

    // 2) QKV mma GEMM (3-stage ring + ldmatrix)
    cudaFuncSetAttribute(qkv_mma_kernel,
                         cudaFuncAttributeMaxDynamicSharedMemorySize, GEMM_SMEM);
    qkv_mma_kernel<<<dim3(L_ / 128, 6, B_), 256, GEMM_SMEM>>>();

    // 3) Attention (frozen R9+LDSM config)
    attn_kernel<<<dim3(L_ / 128, B_ * NH_), 128, ATTN_SMEM_H * 2>>>(ot);

    // 4) proj mma GEMM (3-stage ring + ldmatrix) + bias + residual
    cudaFuncSetAttribute(proj_mma_kernel,
                         cudaFuncAttributeMaxDynamicSharedMemorySize, GEMM_SMEM);
    proj_mma_kernel<<<dim3(L_ / 128, 2, B_), 256, GEMM_SMEM>>>(proj_b, x, out);
}

// round 17
// speedup vs baseline: 1.2508x; 1.0781x over previous
#include <cuda_runtime.h>
#include <cuda_fp16.h>
#include <cstdint>

// ---------------------------------------------------------------------------
// AttentionBlock, fully tensor-core (fp16 mma.m16n8k16, fp32 accum):
//   GroupNorm (fp16 transposed) + fused weight conversion
//   -> QKV mma GEMM (3-stage cp.async ring, ldmatrix fragments)
//   -> FA-2 flash attention, SPLIT-KV x2 (R9+LDSM skeleton; fp32 partials)
//   -> combine (normalize) -> proj mma GEMM (3-stage ring) + residual.
// B=4, C=256, L=4096, 4 heads, d=64.
// ---------------------------------------------------------------------------

namespace {
constexpr int B_  = 4;
constexpr int C_  = 256;
constexpr int L_  = 4096;
constexpr int G_  = 32;
constexpr int NH_ = 4;
constexpr int CPG_ = C_ / G_;
constexpr float QSCALE = 0.125f * 1.4426950408889634f;   // d^-0.5 * log2(e)
// attention smem offsets (in halves): K 64x72 tiles, V 72x72 tiles
constexpr int KOFF0 = 0;
constexpr int KOFF1 = 4608;
constexpr int VOFF0 = 9216;
constexpr int VOFF1 = 14400;
constexpr int ATTN_SMEM_H = 19584;                       // halves -> 39168 B
// gemm smem: 3 stages x (A 128x72 + B 128x72) halves; stage = 9216 u32
constexpr int GEMM_SMEM = 3 * 9216 * 4;                  // 110592 B
}

// ---- fp16 mma (fp32 accumulate) ----
__device__ __forceinline__ void mma_f16(float c[4], const uint32_t a[4],
                                        uint32_t b0, uint32_t b1) {
    asm volatile(
        "mma.sync.aligned.m16n8k16.row.col.f32.f16.f16.f32 "
        "{%0,%1,%2,%3},{%4,%5,%6,%7},{%8,%9},{%0,%1,%2,%3};"
        : "+f"(c[0]), "+f"(c[1]), "+f"(c[2]), "+f"(c[3])
        : "r"(a[0]), "r"(a[1]), "r"(a[2]), "r"(a[3]), "r"(b0), "r"(b1));
}
__device__ __forceinline__ uint32_t h2u(float x, float y) {
    __half2 h = __floats2half2_rn(x, y);
    return *reinterpret_cast<uint32_t*>(&h);
}
__device__ __forceinline__ uint32_t ex2h2(float x, float y) {
    uint32_t h = h2u(x, y), r;
    asm("ex2.approx.f16x2 %0, %1;" : "=r"(r) : "r"(h));
    return r;
}
__device__ __forceinline__ uint32_t smem_u32p(const void* p) {
    uint32_t a;
    asm("{ .reg .u64 t; cvta.to.shared.u64 t, %1; cvt.u32.u64 %0, t; }" : "=r"(a) : "l"(p));
    return a;
}
#define CP_ASYNC16(dst, src) \
    asm volatile("cp.async.cg.shared.global [%0], [%1], 16;" :: "r"(dst), "l"(src))
#define CP_COMMIT() asm volatile("cp.async.commit_group;")
#define LDSM_X4(r0, r1, r2, r3, addr) \
    asm volatile("ldmatrix.sync.aligned.m8n8.x4.shared.b16 {%0,%1,%2,%3}, [%4];" \
                 : "=r"(r0), "=r"(r1), "=r"(r2), "=r"(r3) : "r"(addr))
#define LDSM_X2(r0, r1, addr) \
    asm volatile("ldmatrix.sync.aligned.m8n8.x2.shared.b16 {%0,%1}, [%2];" \
                 : "=r"(r0), "=r"(r1) : "r"(addr))

// ---- scratch (device globals) ----
__device__ __half g_ht[B_ * L_ * C_];        // GN output transposed (b, l, c)
__device__ __half g_q [B_ * NH_ * L_ * 64];  // (bh, l, d), prescaled by QSCALE
__device__ __half g_k [B_ * NH_ * L_ * 64];  // (bh, l, d)
__device__ __half g_v [B_ * NH_ * 64 * L_];  // (bh, d, l)
__device__ __half g_ot[B_ * L_ * C_];        // attention out transposed (b, l, c)
__device__ float  g_part[2 * 16 * L_ * 72];  // split-KV partials (37.7 MB)
__device__ __half g_wh[768 * 256];           // qkv weights fp16 (Q rows prescaled)
__device__ __half g_wp[256 * 256];           // proj weights fp16
__device__ float  g_bs[768];                 // qkv bias (Q prescaled)
__device__ float  g_mean[B_ * G_];
__device__ float  g_rstd[B_ * G_];

// ---------------------------------------------------------------------------
// Fused GroupNorm stats + weight/bias conversion.
// blocks 0..127: stats for (batch, group). blocks 128..1151: wconv rows.
// ---------------------------------------------------------------------------
__global__ void gn_stats_wconv_kernel(const float* __restrict__ x,
                                      const float* __restrict__ qkvw,
                                      const float* __restrict__ projw,
                                      const float* __restrict__ qkvb) {
    if (blockIdx.x >= 128) {
        const int row = blockIdx.x - 128, t = threadIdx.x;
        if (row < 768) {
            const float s = (row < 256) ? QSCALE : 1.f;
            g_wh[row * 256 + t] = __float2half_rn(qkvw[row * 256 + t] * s);
            if (t == 0) g_bs[row] = qkvb[row] * s;
        } else {
            const int r = row - 768;
            g_wp[r * 256 + t] = __float2half_rn(projw[r * 256 + t]);
        }
        return;
    }
    const int bg = blockIdx.x;
    const float4* p = reinterpret_cast<const float4*>(x) + (size_t)bg * (CPG_ * L_ / 4);
    float s = 0.f, ss = 0.f;
    for (int i = threadIdx.x; i < CPG_ * L_ / 4; i += blockDim.x) {
        float4 v = p[i];
        s  += v.x + v.y + v.z + v.w;
        ss += v.x * v.x + v.y * v.y + v.z * v.z + v.w * v.w;
    }
#pragma unroll
    for (int o = 16; o > 0; o >>= 1) {
        s  += __shfl_xor_sync(0xffffffffu, s, o);
        ss += __shfl_xor_sync(0xffffffffu, ss, o);
    }
    __shared__ float sh_s[8], sh_ss[8];
    const int w = threadIdx.x >> 5;
    if ((threadIdx.x & 31) == 0) { sh_s[w] = s; sh_ss[w] = ss; }
    __syncthreads();
    if (threadIdx.x == 0) {
        float S = 0.f, SS = 0.f;
#pragma unroll
        for (int i = 0; i < 8; i++) { S += sh_s[i]; SS += sh_ss[i]; }
        const float inv = 1.f / (float)(CPG_ * L_);
        const float mean = S * inv;
        const float var  = SS * inv - mean * mean;
        g_mean[bg] = mean;
        g_rstd[bg] = rsqrtf(var + 1e-5f);
    }
}

// ---------------------------------------------------------------------------
// GroupNorm apply, emitting fp16 h^T as (b, l, c)
// ---------------------------------------------------------------------------
__global__ void gn_apply_t_kernel(const float* __restrict__ x,
                                  const float* __restrict__ w,
                                  const float* __restrict__ bvec) {
    __shared__ __half Ts[64 * 40];
    const int b  = blockIdx.z;
    const int c0 = blockIdx.y * 32;
    const int l0 = blockIdx.x * 64;
    const int tid = threadIdx.x;
#pragma unroll
    for (int i = 0; i < 2; i++) {
        const int e = tid + i * 256;
        const int r = e >> 4;
        const int l4 = (e & 15) * 4;
        const int c = c0 + r;
        const int bg = b * G_ + (c >> 3);
        const float sc = g_rstd[bg] * w[c];
        const float sh = bvec[c] - g_mean[bg] * sc;
        float4 v = *reinterpret_cast<const float4*>(
            x + ((size_t)b * C_ + c) * L_ + l0 + l4);
        Ts[(l4 + 0) * 40 + r] = __float2half_rn(v.x * sc + sh);
        Ts[(l4 + 1) * 40 + r] = __float2half_rn(v.y * sc + sh);
        Ts[(l4 + 2) * 40 + r] = __float2half_rn(v.z * sc + sh);
        Ts[(l4 + 3) * 40 + r] = __float2half_rn(v.w * sc + sh);
    }
    __syncthreads();
    const int r = tid >> 2;
    const int q4 = (tid & 3) * 8;
    *reinterpret_cast<uint4*>(g_ht + ((size_t)b * L_ + l0 + r) * C_ + c0 + q4) =
        *reinterpret_cast<const uint4*>(Ts + r * 40 + q4);
}

// ---------------------------------------------------------------------------
// QKV GEMM (fp16 mma, 3-stage cp.async ring, ldmatrix fragments).
// grid (L/128, 6, B), 256 threads. Epilogue routes Q,K -> (bh,l,d),
// V -> (bh,d,l).
// ---------------------------------------------------------------------------
__global__ void __launch_bounds__(256) qkv_mma_kernel() {
    extern __shared__ __align__(16) char smraw[];
    const uint32_t sb = smem_u32p(smraw);
    __half* Csh = reinterpret_cast<__half*>(smraw);
    uint32_t* Csu = reinterpret_cast<uint32_t*>(smraw);

    const int tid = threadIdx.x, wid = tid >> 5, lane = tid & 31;
    const int lg = lane >> 2, lt = lane & 3;
    const int nt = blockIdx.x, mt = blockIdx.y, b = blockIdx.z;
    const int m0 = mt * 128, n0g = nt * 128;
    const int moff = (wid & 3) * 32, noff = (wid >> 2) * 64;
    const __half* wsrc = g_wh;
    const __half* hsrc = g_ht + ((size_t)b * L_ + n0g) * 256;

    const int r8 = lane & 7;
    const uint32_t aOff = (uint32_t)((moff + ((lane >> 3) & 1) * 8 + r8) * 144 +
                                     ((lane >> 4) & 1) * 16);
    const uint32_t bOff = (uint32_t)((noff + ((lane >> 4) & 1) * 8 + r8) * 144 +
                                     ((lane >> 3) & 1) * 16);

    auto issueAB = [&](int kc, uint32_t ub /*u32 stage base*/) {
#pragma unroll
        for (int i = 0; i < 4; i++) {
            const int e = tid + i * 256;
            const int r = e >> 3, c8 = (e & 7) * 8;
            CP_ASYNC16(sb + ub * 4 + r * 144 + c8 * 2,
                       wsrc + (size_t)(m0 + r) * 256 + kc * 64 + c8);
            CP_ASYNC16(sb + (ub + 4608) * 4 + r * 144 + c8 * 2,
                       hsrc + (size_t)r * 256 + kc * 64 + c8);
        }
        CP_COMMIT();
    };

    issueAB(0, 0);
    issueAB(1, 9216);

    float oc[2][8][4] = {};
    uint32_t scb = 0, snb = 18432;
    for (int k = 0; k < 4; k++) {
        if (k < 3) asm volatile("cp.async.wait_group 1;" ::: "memory");
        else       asm volatile("cp.async.wait_group 0;" ::: "memory");
        __syncthreads();
        if (k + 2 < 4) issueAB(k + 2, snb);
        const uint32_t abase = sb + scb * 4 + aOff;
        const uint32_t bbase = sb + (scb + 4608) * 4 + bOff;
#pragma unroll
        for (int kc = 0; kc < 4; kc++) {
            uint32_t a[2][4];
            LDSM_X4(a[0][0], a[0][1], a[0][2], a[0][3], abase + (uint32_t)(kc * 32));
            LDSM_X4(a[1][0], a[1][1], a[1][2], a[1][3], abase + (uint32_t)(2304 + kc * 32));
#pragma unroll
            for (int p = 0; p < 4; p++) {
                uint32_t v0, v1, v2, v3;
                LDSM_X4(v0, v1, v2, v3, bbase + (uint32_t)(p * 2304 + kc * 32));
                mma_f16(oc[0][2 * p],     a[0], v0, v1);
                mma_f16(oc[1][2 * p],     a[1], v0, v1);
                mma_f16(oc[0][2 * p + 1], a[0], v2, v3);
                mma_f16(oc[1][2 * p + 1], a[1], v2, v3);
            }
        }
        scb = (scb == 18432) ? 0 : scb + 9216;
        snb = (snb == 18432) ? 0 : snb + 9216;
    }
    __syncthreads();

    const int sel = mt >> 1;
    const int h0 = (mt & 1) * 2;
    float bv[2][2];
#pragma unroll
    for (int m = 0; m < 2; m++) {
        bv[m][0] = g_bs[m0 + moff + m * 16 + lg];
        bv[m][1] = g_bs[m0 + moff + m * 16 + lg + 8];
    }

    if (sel < 2) {
#pragma unroll
        for (int m = 0; m < 2; m++) {
            const int r = moff + m * 16 + lg;
#pragma unroll
            for (int n = 0; n < 8; n++) {
                const int col = noff + n * 8 + 2 * lt;
                Csh[col * 136 + r]           = __float2half_rn(oc[m][n][0] + bv[m][0]);
                Csh[(col + 1) * 136 + r]     = __float2half_rn(oc[m][n][1] + bv[m][0]);
                Csh[col * 136 + r + 8]       = __float2half_rn(oc[m][n][2] + bv[m][1]);
                Csh[(col + 1) * 136 + r + 8] = __float2half_rn(oc[m][n][3] + bv[m][1]);
            }
        }
        __syncthreads();
        __half* dst = (sel == 0 ? g_q : g_k);
#pragma unroll
        for (int i = 0; i < 8; i++) {
            const int e = tid + i * 256;
            const int l = e >> 4;
            const int seg = e & 15;
            const int hd = seg >> 3, q8 = (seg & 7) * 8;
            *reinterpret_cast<uint4*>(
                dst + ((size_t)(b * NH_ + h0 + hd) * L_ + n0g + l) * 64 + q8) =
                *reinterpret_cast<const uint4*>(Csh + l * 136 + hd * 64 + q8);
        }
    } else {
#pragma unroll
        for (int m = 0; m < 2; m++) {
            const int r = moff + m * 16 + lg;
#pragma unroll
            for (int n = 0; n < 8; n++) {
                const int cu = (noff >> 1) + n * 4 + lt;
                Csu[r * 68 + cu]       = h2u(oc[m][n][0] + bv[m][0], oc[m][n][1] + bv[m][0]);
                Csu[(r + 8) * 68 + cu] = h2u(oc[m][n][2] + bv[m][1], oc[m][n][3] + bv[m][1]);
            }
        }
        __syncthreads();
#pragma unroll
        for (int i = 0; i < 8; i++) {
            const int e = tid + i * 256;
            const int r = e >> 4;
            const int c8 = (e & 15) * 8;
            const int hd = r >> 6, d = r & 63;
            *reinterpret_cast<uint4*>(
                g_v + ((size_t)((b * NH_ + h0 + hd) * 64 + d)) * L_ + n0g + c8) =
                *reinterpret_cast<const uint4*>(Csh + r * 136 + c8);
        }
    }
}

// ---------------------------------------------------------------------------
// Flash attention — R9+LDSM skeleton, SPLIT-KV x2.
// grid (32, 16, 2): z = KV half. Each CTA: 128 queries x 2048 keys (32 tiles),
// writes UNNORMALIZED fp32 partial O (+ ones-row sum at col 64) to g_part.
// ---------------------------------------------------------------------------
__global__ void __launch_bounds__(128, 3) attn_kernel() {
    extern __shared__ __align__(16) __half smh[];
    uint32_t* smu = reinterpret_cast<uint32_t*>(smh);
    const uint32_t sb = smem_u32p(smh);

    const int tid = threadIdx.x, wid = tid >> 5, lane = tid & 31;
    const int lg = lane >> 2, lt = lane & 3;
    const int qb = wid * 32;
    const int l0 = blockIdx.x * 128;
    const int bh = blockIdx.y;
    const int half = blockIdx.z;
    const __half* qg = g_q + ((size_t)bh * L_ + l0) * 64;
    const __half* kg = g_k + (size_t)bh * L_ * 64;
    const __half* vg = g_v + (size_t)bh * 64 * L_;

    const int r8 = lane & 7, lsel = lane >> 3;
    const uint32_t bfragOff = (uint32_t)(((lsel >> 1) * 8 + r8) * 144 + (lsel & 1) * 16);
    const uint32_t onesOff  = (uint32_t)((64 + (lane & 7)) * 144 + ((lane >> 3) & 1) * 16);

    for (int e = tid; e < 576; e += 128) {
        const int buf = e / 288, rem = e % 288;
        const int row = 64 + rem / 36, c = rem % 36;
        smu[(((buf ? VOFF1 : VOFF0) + row * 72) >> 1) + c] =
            (row == 64) ? 0x3C003C00u : 0u;
    }
#pragma unroll
    for (int i = 0; i < 8; i++) {
        const int e = tid + i * 128;
        const int r = e >> 3, c8 = (e & 7) * 8;
        *reinterpret_cast<uint4*>(smh + r * 72 + c8) =
            *reinterpret_cast<const uint4*>(qg + (size_t)r * 64 + c8);
    }
    __syncthreads();
    uint32_t qa[2][4][4];
#pragma unroll
    for (int m = 0; m < 2; m++) {
        const int r0 = qb + m * 16 + lg;
#pragma unroll
        for (int kc = 0; kc < 4; kc++) {
            qa[m][kc][0] = smu[r0 * 36 + kc * 8 + lt];
            qa[m][kc][1] = smu[(r0 + 8) * 36 + kc * 8 + lt];
            qa[m][kc][2] = smu[r0 * 36 + kc * 8 + lt + 4];
            qa[m][kc][3] = smu[(r0 + 8) * 36 + kc * 8 + lt + 4];
        }
    }
    __syncthreads();

    auto issue = [&](int tile, uint32_t koff, uint32_t voff) {
        const __half* ks = kg + (size_t)tile * 64 * 64;
        const __half* vs = vg + tile * 64;
#pragma unroll
        for (int i = 0; i < 4; i++) {
            const int e = tid + i * 128;
            const int r = e >> 3, c8 = (e & 7) * 8;
            CP_ASYNC16(sb + (koff + r * 72 + c8) * 2, ks + (size_t)r * 64 + c8);
            CP_ASYNC16(sb + (voff + r * 72 + c8) * 2, vs + (size_t)r * L_ + c8);
        }
        CP_COMMIT();
    };

    const int t0 = half * 32;
    float oc[2][9][4] = {};
    issue(t0, KOFF0, VOFF0);

    for (int it = 0; it < 32; ++it) {
        const int cur = it & 1;
        const uint32_t koff = cur ? KOFF1 : KOFF0;
        const uint32_t voff = cur ? VOFF1 : VOFF0;
        if (it < 31) {
            issue(t0 + it + 1, cur ? KOFF0 : KOFF1, cur ? VOFF0 : VOFF1);
            asm volatile("cp.async.wait_group 1;" ::: "memory");
        } else {
            asm volatile("cp.async.wait_group 0;" ::: "memory");
        }
        __syncthreads();
        const uint32_t kbase = sb + koff * 2 + bfragOff;
        const uint32_t vbase = sb + voff * 2 + bfragOff;
        const uint32_t obase = sb + voff * 2 + onesOff;

#pragma unroll
        for (int kb = 0; kb < 4; kb++) {
            float ca0[4] = {}, cb0[4] = {}, ca1[4] = {}, cb1[4] = {};
#pragma unroll
            for (int kc = 0; kc < 4; kc++) {
                uint32_t x0, x1, x2, x3;
                LDSM_X4(x0, x1, x2, x3, kbase + (uint32_t)(kb * 2304 + kc * 32));
                mma_f16(ca0, qa[0][kc], x0, x1);
                mma_f16(cb0, qa[1][kc], x0, x1);
                mma_f16(ca1, qa[0][kc], x2, x3);
                mma_f16(cb1, qa[1][kc], x2, x3);
            }
            uint32_t pa0[4] = {ex2h2(ca0[0], ca0[1]), ex2h2(ca0[2], ca0[3]),
                               ex2h2(ca1[0], ca1[1]), ex2h2(ca1[2], ca1[3])};
            uint32_t pa1[4] = {ex2h2(cb0[0], cb0[1]), ex2h2(cb0[2], cb0[3]),
                               ex2h2(cb1[0], cb1[1]), ex2h2(cb1[2], cb1[3])};
#pragma unroll
            for (int p = 0; p < 4; p++) {
                uint32_t v0, v1, v2, v3;
                LDSM_X4(v0, v1, v2, v3, vbase + (uint32_t)(p * 2304 + kb * 32));
                mma_f16(oc[0][2 * p],     pa0, v0, v1);
                mma_f16(oc[1][2 * p],     pa1, v0, v1);
                mma_f16(oc[0][2 * p + 1], pa0, v2, v3);
                mma_f16(oc[1][2 * p + 1], pa1, v2, v3);
            }
            {
                uint32_t w0, w1;
                LDSM_X2(w0, w1, obase + (uint32_t)(kb * 32));
                mma_f16(oc[0][8], pa0, w0, w1);
                mma_f16(oc[1][8], pa1, w0, w1);
            }
        }
        __syncthreads();
    }

    // ---- write unnormalized fp32 partials: rows (l0+q), 72-float stride ----
    float* pp = g_part + ((size_t)(half * 16 + bh) * L_ + l0) * 72;
#pragma unroll
    for (int m = 0; m < 2; m++) {
        float* r0p = pp + (size_t)(qb + m * 16 + lg) * 72;
        float* r1p = r0p + 8 * 72;
#pragma unroll
        for (int n = 0; n < 9; n++) {
            *reinterpret_cast<float2*>(r0p + n * 8 + 2 * lt) =
                make_float2(oc[m][n][0], oc[m][n][1]);
            *reinterpret_cast<float2*>(r1p + n * 8 + 2 * lt) =
                make_float2(oc[m][n][2], oc[m][n][3]);
        }
    }
}

// ---------------------------------------------------------------------------
// Split-KV combine: out = (p0 + p1) / (s0 + s1), fp16 (b, l, c) layout.
// grid (32, 16), 256 threads.
// ---------------------------------------------------------------------------
__global__ void __launch_bounds__(256) attn_combine_kernel(__half* __restrict__ ot) {
    const int bh = blockIdx.y, b = bh >> 2, head = bh & 3;
    const int l0 = blockIdx.x * 128;
    const float* p0 = g_part + ((size_t)bh * L_ + l0) * 72;
    const float* p1 = p0 + (size_t)16 * L_ * 72;
    __half* otp = ot + ((size_t)b * L_ + l0) * C_ + head * 64;
#pragma unroll
    for (int i = 0; i < 4; i++) {
        const int e = threadIdx.x + i * 256;     // 1024 units
        const int l = e >> 3, c8 = (e & 7) * 8;
        const float* r0 = p0 + (size_t)l * 72;
        const float* r1 = p1 + (size_t)l * 72;
        const float inv = 1.f / (r0[64] + r1[64]);
        float4 a0 = *reinterpret_cast<const float4*>(r0 + c8);
        float4 a1 = *reinterpret_cast<const float4*>(r0 + c8 + 4);
        float4 b0 = *reinterpret_cast<const float4*>(r1 + c8);
        float4 b1 = *reinterpret_cast<const float4*>(r1 + c8 + 4);
        uint4 o;
        o.x = h2u((a0.x + b0.x) * inv, (a0.y + b0.y) * inv);
        o.y = h2u((a0.z + b0.z) * inv, (a0.w + b0.w) * inv);
        o.z = h2u((a1.x + b1.x) * inv, (a1.y + b1.y) * inv);
        o.w = h2u((a1.z + b1.z) * inv, (a1.w + b1.w) * inv);
        *reinterpret_cast<uint4*>(otp + (size_t)l * C_ + c8) = o;
    }
}

// ---------------------------------------------------------------------------
// proj GEMM (fp16 mma, 3-stage ring, ldmatrix fragments) + bias + residual
// grid (L/128, 2, B), 256 threads
// ---------------------------------------------------------------------------
__global__ void __launch_bounds__(256) proj_mma_kernel(
    const float* __restrict__ projb, const float* __restrict__ x,
    float* __restrict__ out)
{
    extern __shared__ __align__(16) char smraw[];
    const uint32_t sb = smem_u32p(smraw);

    const int tid = threadIdx.x, wid = tid >> 5, lane = tid & 31;
    const int lg = lane >> 2, lt = lane & 3;
    const int nt = blockIdx.x, mt = blockIdx.y, b = blockIdx.z;
    const int m0 = mt * 128, n0g = nt * 128;
    const int moff = (wid & 3) * 32, noff = (wid >> 2) * 64;
    const __half* wsrc = g_wp;
    const __half* osrc = g_ot + ((size_t)b * L_ + n0g) * 256;

    const int r8 = lane & 7;
    const uint32_t aOff = (uint32_t)((moff + ((lane >> 3) & 1) * 8 + r8) * 144 +
                                     ((lane >> 4) & 1) * 16);
    const uint32_t bOff = (uint32_t)((noff + ((lane >> 4) & 1) * 8 + r8) * 144 +
                                     ((lane >> 3) & 1) * 16);

    auto issueAB = [&](int kc, uint32_t ub) {
#pragma unroll
        for (int i = 0; i < 4; i++) {
            const int e = tid + i * 256;
            const int r = e >> 3, c8 = (e & 7) * 8;
            CP_ASYNC16(sb + ub * 4 + r * 144 + c8 * 2,
                       wsrc + (size_t)(m0 + r) * 256 + kc * 64 + c8);
            CP_ASYNC16(sb + (ub + 4608) * 4 + r * 144 + c8 * 2,
                       osrc + (size_t)r * 256 + kc * 64 + c8);
        }
        CP_COMMIT();
    };
    issueAB(0, 0);
    issueAB(1, 9216);

    float oc[2][8][4] = {};
    uint32_t scb = 0, snb = 18432;
    for (int k = 0; k < 4; k++) {
        if (k < 3) asm volatile("cp.async.wait_group 1;" ::: "memory");
        else       asm volatile("cp.async.wait_group 0;" ::: "memory");
        __syncthreads();
        if (k + 2 < 4) issueAB(k + 2, snb);
        const uint32_t abase = sb + scb * 4 + aOff;
        const uint32_t bbase = sb + (scb + 4608) * 4 + bOff;
#pragma unroll
        for (int kc = 0; kc < 4; kc++) {
            uint32_t a[2][4];
            LDSM_X4(a[0][0], a[0][1], a[0][2], a[0][3], abase + (uint32_t)(kc * 32));
            LDSM_X4(a[1][0], a[1][1], a[1][2], a[1][3], abase + (uint32_t)(2304 + kc * 32));
#pragma unroll
            for (int p = 0; p < 4; p++) {
                uint32_t v0, v1, v2, v3;
                LDSM_X4(v0, v1, v2, v3, bbase + (uint32_t)(p * 2304 + kc * 32));
                mma_f16(oc[0][2 * p],     a[0], v0, v1);
                mma_f16(oc[1][2 * p],     a[1], v0, v1);
                mma_f16(oc[0][2 * p + 1], a[0], v2, v3);
                mma_f16(oc[1][2 * p + 1], a[1], v2, v3);
            }
        }
        scb = (scb == 18432) ? 0 : scb + 9216;
        snb = (snb == 18432) ? 0 : snb + 9216;
    }
#pragma unroll
    for (int m = 0; m < 2; m++) {
        const int crow = m0 + moff + m * 16 + lg;
        const float b0v = projb[crow], b1v = projb[crow + 8];
        const float* xp0 = x   + ((size_t)b * C_ + crow) * L_;
        float*       op0 = out + ((size_t)b * C_ + crow) * L_;
#pragma unroll
        for (int n = 0; n < 8; n++) {
            const int col = n0g + noff + n * 8 + 2 * lt;
            float2 xr = *reinterpret_cast<const float2*>(xp0 + col);
            *reinterpret_cast<float2*>(op0 + col) =
                make_float2(oc[m][n][0] + b0v + xr.x, oc[m][n][1] + b0v + xr.y);
            float2 xr2 = *reinterpret_cast<const float2*>(xp0 + 8 * L_ + col);
            *reinterpret_cast<float2*>(op0 + 8 * L_ + col) =
                make_float2(oc[m][n][2] + b1v + xr2.x, oc[m][n][3] + b1v + xr2.y);
        }
    }
}

// ---------------------------------------------------------------------------
// Host launcher
// ---------------------------------------------------------------------------
extern "C" void kernel_launch(void* const* d_in, const int* in_sizes, int n_in,
                              void* d_out, int out_size) {
    (void)in_sizes; (void)n_in; (void)out_size;
    const float* x      = (const float*)d_in[0];
    const float* gn_w   = (const float*)d_in[1];
    const float* gn_b   = (const float*)d_in[2];
    const float* qkv_w  = (const float*)d_in[3];
    const float* qkv_b  = (const float*)d_in[4];
    const float* proj_w = (const float*)d_in[5];
    const float* proj_b = (const float*)d_in[6];
    float* out = (float*)d_out;

    void* pot;
    cudaGetSymbolAddress(&pot, g_ot);
    __half* ot = (__half*)pot;

    // 1) Fused GroupNorm stats + weight conversion, then GN apply
    gn_stats_wconv_kernel<<<1152, 256>>>(x, qkv_w, proj_w, qkv_b);
    gn_apply_t_kernel<<<dim3(L_ / 64, C_ / 32, B_), 256>>>(x, gn_w, gn_b);

    // 2) QKV mma GEMM (3-stage ring + ldmatrix)
    cudaFuncSetAttribute(qkv_mma_kernel,
                         cudaFuncAttributeMaxDynamicSharedMemorySize, GEMM_SMEM);
    qkv_mma_kernel<<<dim3(L_ / 128, 6, B_), 256, GEMM_SMEM>>>();

    // 3) Attention, split-KV x2 -> fp32 partials, then combine
    attn_kernel<<<dim3(L_ / 128, B_ * NH_, 2), 128, ATTN_SMEM_H * 2>>>();
    attn_combine_kernel<<<dim3(L_ / 128, B_ * NH_), 256>>>(ot);

    // 4) proj mma GEMM (3-stage ring + ldmatrix) + bias + residual
    cudaFuncSetAttribute(proj_mma_kernel,
                         cudaFuncAttributeMaxDynamicSharedMemorySize, GEMM_SMEM);
    proj_mma_kernel<<<dim3(L_ / 128, 2, B_), 256, GEMM_SMEM>>>(proj_b, x, out);
}